// round 7
// baseline (speedup 1.0000x reference)
#include <cuda_runtime.h>
#include <math.h>
#include <stdint.h>

#define NB   32
#define TT   512
#define NIN  50
#define HH   512
#define OUTF 66
#define MAXP 10
#define NJS  32     // j-slices (16 h-units each)
#define NBG  4      // independent batch groups
#define GB   8      // batches per group
#define JSL  16
#define NTHR 512
#define NCTA 128

// ---------------- persistent device scratch (allocation-free) ----------------
__device__ float    g_h[2][NB][HH];          // double-buffered h exchange
__device__ float    g_haltp[2][NJS][NB];     // halt-dot partials, dbl-buffered by n parity
__device__ float    g_ypart[NJS][NB][OUTF];  // per-slice acc_y partials (1 full barrier between use)
__device__ unsigned g_barcnt[NBG * 32];      // padded to 128B lines
__device__ unsigned g_barflag[NBG * 32];
__device__ unsigned g_exitcnt[NBG * 32];

__device__ __forceinline__ float sigm(float v) { return 1.0f / (1.0f + expf(-v)); }

// Per-batch-group grid barrier (32 CTAs). Monotone counter + flag; flag/cnt are
// reset by the exit sequence so state is clean for every graph replay.
// __threadfence (gpu scope) emits CCTL.IVALL on sm_103a -> pre-arrive it drains
// our stores to L2; post-release it invalidates L1D so reads see peers' writes.
__device__ __forceinline__ void bar_bg(int bg, unsigned &lgen) {
    __threadfence();
    __syncthreads();
    lgen++;
    if (threadIdx.x == 0) {
        unsigned* cnt = &g_barcnt[bg * 32];
        unsigned* flg = &g_barflag[bg * 32];
        unsigned a = atomicAdd(cnt, 1u);
        if (a == lgen * 32u - 1u) {        // last arriver of barrier #lgen
            atomicExch(flg, lgen);
        } else {
            while (atomicAdd(flg, 0u) < lgen) { __nanosleep(64); }
        }
        __threadfence();
    }
    __syncthreads();
}

__global__ void __launch_bounds__(NTHR, 1)
act_lstm_kernel(const float* __restrict__ x,      // [32,512,50]
                const float* __restrict__ Wih,    // [2048,51]
                const float* __restrict__ Whh,    // [2048,512]
                const float* __restrict__ bias,   // [2048]
                const float* __restrict__ Wout,   // [66,512]
                const float* __restrict__ bout,   // [66]
                const float* __restrict__ Whalt,  // [512]
                const float* __restrict__ bhaltp, // [1]
                float* __restrict__ out)          // [32*512*66] out ++ [32*512] p
{
    const int bg     = blockIdx.x >> 5;   // 0..3
    const int js     = blockIdx.x & 31;   // 0..31
    const int bgbase = bg * GB;
    const int tid    = threadIdx.x;
    const int rowl   = tid >> 3;          // 0..63 : gate-row within CTA
    const int bl     = tid & 7;           // 0..7  : batch within group
    const int gtype  = rowl >> 4;         // 0..3  : i,f,g,o
    const int jloc   = rowl & 15;
    const int grow   = gtype * HH + js * JSL + jloc;   // global gate row
    const float bhalt = bhaltp[0];
    float* pout = out + (size_t)NB * TT * OUTF;

    __shared__ __align__(16) float h_sh[8 * 516];   // h staged, padded (conflict-free f4)
    __shared__ float gate_sh[512];
    __shared__ float h2_sh[128];
    __shared__ float c_sh[128];
    __shared__ float acch[128];
    __shared__ float accc[128];
    __shared__ float accy[528];
    __shared__ float ypre[528];
    __shared__ float hw_sh[128];                    // halt products / reused as y-out
    __shared__ float x_sh[8 * 52];
    __shared__ float cum_s[8], nupd_s[8], rem_s[8], p_s[8], psum_s[8], psump[8];
    __shared__ int   done_s[8], alldone_s;
    __shared__ float m_sh[6], s_sh[6];

    unsigned lgen = 0;
    const float gxf  = Wih[grow * 51 + 50];  // ACT first-step flag column
    const float brow = bias[grow];
    float gx0;                               // x_t contribution for this (row,b)

    // ---------------- prologue: t = 0 state ----------------
    if (tid < 128) {
        g_h[0][bgbase + (tid & 7)][js * JSL + (tid >> 3)] = 0.0f;
        c_sh[tid] = 0.0f; acch[tid] = 0.0f; accc[tid] = 0.0f;
    }
    for (int idx = tid; idx < 528; idx += NTHR) accy[idx] = 0.0f;
    if (tid < 8) {
        cum_s[tid] = 0.0f; nupd_s[tid] = 0.0f; rem_s[tid] = 0.0f;
        psum_s[tid] = 0.0f; done_s[tid] = 0;
    }
    for (int i = tid; i < 8 * NIN; i += NTHR) {
        int bb = i / NIN, k = i - bb * NIN;
        x_sh[bb * 52 + k] = x[((size_t)(bgbase + bb) * TT + 0) * NIN + k];
    }
    __syncthreads();
    {
        float s = brow;
        const float* wih = Wih + (size_t)grow * 51;
        #pragma unroll
        for (int k = 0; k < NIN; k++) s += x_sh[bl * 52 + k] * wih[k];
        gx0 = s;
    }
    bar_bg(bg, lgen);   // g_h[0] zeros visible across the group
    int cur = 0;

    // ================= time loop =================
    for (int t = 0; t < TT; t++) {
        // ---------- adaptive ponder loop ----------
        for (int n = 0; n < MAXP; n++) {
            // stage h (full 512 for 8 batches)
            for (int i = tid; i < 8 * HH; i += NTHR) {
                int bb = i >> 9, k = i & 511;
                h_sh[bb * 516 + k] = g_h[cur][bgbase + bb][k];
            }
            __syncthreads();

            // gate GEMM: one (row,b) accumulator per thread, K = 512
            float a0 = 0.f, a1 = 0.f, a2 = 0.f, a3 = 0.f;
            {
                const float4* wr = reinterpret_cast<const float4*>(Whh + (size_t)grow * HH);
                const float4* hr = reinterpret_cast<const float4*>(h_sh + bl * 516);
                #pragma unroll 8
                for (int k4 = 0; k4 < 128; k4++) {
                    float4 w = wr[k4]; float4 hv = hr[k4];
                    a0 += w.x * hv.x; a1 += w.y * hv.y;
                    a2 += w.z * hv.z; a3 += w.w * hv.w;
                }
            }
            gate_sh[tid] = gx0 + ((n == 0) ? gxf : 0.0f) + ((a0 + a1) + (a2 + a3));
            __syncthreads();

            // pointwise LSTM cell for this CTA's (16 j, 8 b)
            if (tid < 128) {
                int jl = tid >> 3, bl2 = tid & 7;
                float gi = gate_sh[tid];
                float gf = gate_sh[128 + tid];
                float gg = gate_sh[256 + tid];
                float go = gate_sh[384 + tid];
                float c2 = sigm(gf) * c_sh[tid] + sigm(gi) * tanhf(gg);
                float h2 = sigm(go) * tanhf(c2);
                c_sh[tid]  = c2;
                h2_sh[tid] = h2;
                g_h[cur ^ 1][bgbase + bl2][js * JSL + jl] = h2;
                hw_sh[tid] = h2 * Whalt[js * JSL + jl];
            }
            __syncthreads();

            // halt partial per batch + y partials (pre-p)
            if (tid < 8) {
                float s = 0.f;
                #pragma unroll
                for (int q = 0; q < 16; q++) s += hw_sh[q * 8 + tid];
                g_haltp[n & 1][js][bgbase + tid] = s;
            }
            for (int idx = tid; idx < 528; idx += NTHR) {
                int o = idx >> 3, bl2 = idx & 7;
                const float* wo = Wout + (size_t)o * HH + js * JSL;
                float s = 0.f;
                #pragma unroll
                for (int j = 0; j < 16; j++) s += h2_sh[j * 8 + bl2] * wo[j];
                ypre[idx] = s;
            }

            bar_bg(bg, lgen);   // h2 + halt partials visible group-wide

            // ACT state update (replicated identically in every CTA of the group)
            if (tid < 8) {
                float hd = 0.f;
                #pragma unroll 8
                for (int js2 = 0; js2 < NJS; js2++) hd += g_haltp[n & 1][js2][bgbase + tid];
                float halt = sigm(hd + bhalt);
                int   wasdone = done_s[tid];
                int   halted  = ((cum_s[tid] + halt) > 0.99f) || (n == MAXP - 1);
                float p = wasdone ? 0.0f : (halted ? (1.0f - cum_s[tid]) : halt);
                nupd_s[tid] += wasdone ? 0.0f : 1.0f;
                rem_s[tid]  += (wasdone || !halted) ? 0.0f : (1.0f - cum_s[tid]);
                cum_s[tid]  += wasdone ? 0.0f : halt;
                done_s[tid]  = wasdone || halted;
                p_s[tid]     = p;
                psum_s[tid] += p;
            }
            __syncthreads();
            if (tid == 0) {
                int ad = 1;
                #pragma unroll
                for (int q = 0; q < 8; q++) ad &= done_s[q];
                alldone_s = ad;
            }
            if (tid < 128) {
                float p = p_s[tid & 7];
                acch[tid] += p * h2_sh[tid];
                accc[tid] += p * c_sh[tid];
            }
            for (int idx = tid; idx < 528; idx += NTHR)
                accy[idx] += p_s[idx & 7] * ypre[idx];
            __syncthreads();

            cur ^= 1;
            if (alldone_s) break;   // exact: all further contributions are zero
        }

        // ---------- timestep transition ----------
        if (tid < 128) {
            g_h[cur][bgbase + (tid & 7)][js * JSL + (tid >> 3)] = acch[tid];
            c_sh[tid] = accc[tid];
            acch[tid] = 0.0f; accc[tid] = 0.0f;
        }
        for (int idx = tid; idx < 528; idx += NTHR) {
            g_ypart[js][bgbase + (idx & 7)][idx >> 3] = accy[idx];
            accy[idx] = 0.0f;
        }
        if (tid < 8) {
            if (js == 0) pout[(size_t)(bgbase + tid) * TT + t] = nupd_s[tid] + rem_s[tid];
            psump[tid] = psum_s[tid];
            cum_s[tid] = 0.0f; nupd_s[tid] = 0.0f; rem_s[tid] = 0.0f;
            psum_s[tid] = 0.0f; done_s[tid] = 0;
        }
        // x / gx for t+1 (local; overlaps with the coming barrier)
        if (t + 1 < TT) {
            for (int i = tid; i < 8 * NIN; i += NTHR) {
                int bb = i / NIN, k = i - bb * NIN;
                x_sh[bb * 52 + k] = x[((size_t)(bgbase + bb) * TT + (t + 1)) * NIN + k];
            }
        }
        __syncthreads();
        if (t + 1 < TT) {
            float s = brow;
            const float* wih = Wih + (size_t)grow * 51;
            #pragma unroll
            for (int k = 0; k < NIN; k++) s += x_sh[bl * 52 + k] * wih[k];
            gx0 = s;
        }

        bar_bg(bg, lgen);   // weighted h + y-partials visible group-wide

        // ---------- output for timestep t (CTAs js<8 each own one batch) ----------
        if (js < 8) {
            int b = bgbase + js;
            if (tid < OUTF) {
                float v = bout[tid] * psump[js];       // Σp · b_out
                #pragma unroll 8
                for (int js2 = 0; js2 < NJS; js2++) v += g_ypart[js2][b][tid];
                hw_sh[tid] = v;
            }
            __syncthreads();
            if (tid < 6) {
                float m = -1e30f;
                #pragma unroll
                for (int q = 0; q < 11; q++) m = fmaxf(m, hw_sh[tid * 11 + q]);
                float s = 0.f;
                #pragma unroll
                for (int q = 0; q < 11; q++) s += expf(hw_sh[tid * 11 + q] - m);
                m_sh[tid] = m; s_sh[tid] = s;
            }
            __syncthreads();
            if (tid < OUTF) {
                int d = tid / 11;
                out[((size_t)b * TT + t) * OUTF + tid] =
                    expf(hw_sh[tid] - m_sh[d]) / s_sh[d];
            }
        }
    }

    // ---------------- exit sequence: reset barrier state for the next replay ----------------
    __threadfence();
    __syncthreads();
    if (tid == 0) {
        unsigned a = atomicAdd(&g_exitcnt[bg * 32], 1u);
        if (a == 31u) {
            atomicExch(&g_exitcnt[bg * 32], 0u);
            atomicExch(&g_barcnt[bg * 32], 0u);
            atomicExch(&g_barflag[bg * 32], 0u);
        }
    }
}

extern "C" void kernel_launch(void* const* d_in, const int* in_sizes, int n_in,
                              void* d_out, int out_size) {
    const float* x     = (const float*)d_in[0];
    const float* Wih   = (const float*)d_in[1];
    const float* Whh   = (const float*)d_in[2];
    const float* b     = (const float*)d_in[3];
    const float* Wout  = (const float*)d_in[4];
    const float* bout  = (const float*)d_in[5];
    const float* Whalt = (const float*)d_in[6];
    const float* bhalt = (const float*)d_in[7];
    float* out = (float*)d_out;
    act_lstm_kernel<<<NCTA, NTHR>>>(x, Wih, Whh, b, Wout, bout, Whalt, bhalt, out);
}

// round 8
// speedup vs baseline: 1.2669x; 1.2669x over previous
#include <cuda_runtime.h>
#include <math.h>
#include <stdint.h>

#define NB    32
#define TT    512
#define NIN   50
#define HH    512
#define OUTF  66
#define MAXP  10
#define NJS   32      // CTAs (j-slices) per batch group
#define NBG   4       // independent batch groups
#define GB    8       // batches per group
#define NTHR  512
#define NCTA  128

// ---------------- persistent device scratch (allocation-free) ----------------
__device__ float    g_hstep[2][MAXP][NB][HH];   // per-ponder-step h2, dbl-buffered by t parity
__device__ float    g_haltp[2][NJS][NB];        // halt-dot partials, dbl-buffered by n parity
__device__ float    g_yacc[NB * TT * OUTF];     // pre-softmax logits accumulator (atomic)
__device__ unsigned g_barcnt[NBG * 32];
__device__ unsigned g_barflag[NBG * 32];
__device__ unsigned g_exitcnt[NBG * 32];

__device__ __forceinline__ float sigm(float v) { return 1.0f / (1.0f + expf(-v)); }

// Per-batch-group (32-CTA) barrier. Fences only in thread 0 (cooperative-groups
// pattern): __syncthreads orders all CTA threads' stores at CTA scope; t0's
// fence.gpu + release/acquire around the flag atomic publishes/acquires at GPU
// scope (the acquire-side __threadfence emits CCTL.IVALL -> L1 invalidated, so
// post-barrier loads see peer SMs' writes). SMEM-resident weights are untouched.
__device__ __forceinline__ void bar_bg(int bg, unsigned& lgen) {
    __syncthreads();
    lgen++;
    if (threadIdx.x == 0) {
        __threadfence();                               // release
        unsigned a = atomicAdd(&g_barcnt[bg * 32], 1u);
        if (a == lgen * 32u - 1u) {
            atomicExch(&g_barflag[bg * 32], lgen);
        } else {
            while (atomicAdd(&g_barflag[bg * 32], 0u) < lgen) { __nanosleep(32); }
        }
        __threadfence();                               // acquire (CCTL.IVALL)
    }
    __syncthreads();
}

// dynamic-smem layout (float offsets); all float4 bases 16B-aligned,
// row pads chosen for conflict-free GEMM access (520 mod 32 = 8, 516 mod 32 = 4)
#define WHH_OFF    0        // [64 rows][2 halves][260]  (260-padded 256-halves)
#define WIH_OFF    33280    // [64][52]
#define WOUT_OFF   36608    // [66][16]
#define WHALT_OFF  37664    // [16]
#define H_OFF      37680    // [8][516]
#define DSM_FLOATS 41808    // 167232 bytes

extern __shared__ float dsm[];

__global__ void __launch_bounds__(NTHR, 1)
act_lstm_main(const float* __restrict__ x,       // [32,512,50]
              const float* __restrict__ Wih,     // [2048,51]
              const float* __restrict__ Whh,     // [2048,512]
              const float* __restrict__ bias,    // [2048]
              const float* __restrict__ Wout,    // [66,512]
              const float* __restrict__ Whalt,   // [512]
              const float* __restrict__ bhaltp,  // [1]
              float* __restrict__ pout)          // ponder-cost region of d_out
{
    const int bg     = blockIdx.x >> 5;
    const int js     = blockIdx.x & 31;
    const int bgbase = bg * GB;
    const int tid    = threadIdx.x;
    const int rowl   = tid >> 3;                 // 0..63 local gate row
    const int bl     = tid & 7;                  // 0..7 batch-in-group
    const int grow   = (rowl >> 4) * HH + js * 16 + (rowl & 15);
    const float bhalt = bhaltp[0];

    float* whh_s   = dsm + WHH_OFF;
    float* wih_s   = dsm + WIH_OFF;
    float* wout_s  = dsm + WOUT_OFF;
    float* whalt_s = dsm + WHALT_OFF;
    float* h_sh    = dsm + H_OFF;

    __shared__ float gate_sh[512];
    __shared__ float h2s[128], cs[128], accc[128];
    __shared__ float accy[528], ypre[528];
    __shared__ float hw[128];
    __shared__ float x_sh[GB * 52];
    __shared__ float p_hist[MAXP][8];
    __shared__ float cum_s[8], nupd_s[8], rem_s[8], p_s[8];
    __shared__ int   done_s[8], alldone_sh;

    // ---------------- prologue: stage weight slices into SMEM ----------------
    for (int f4 = tid; f4 < 64 * 128; f4 += NTHR) {
        int r = f4 >> 7, kk = (f4 & 127) << 2;
        int gr = (r >> 4) * HH + js * 16 + (r & 15);
        float4 w = *reinterpret_cast<const float4*>(Whh + (size_t)gr * HH + kk);
        *reinterpret_cast<float4*>(whh_s + r * 520 + (kk >> 8) * 260 + (kk & 255)) = w;
    }
    for (int i = tid; i < 64 * 51; i += NTHR) {
        int r = i / 51, k = i - r * 51;
        int gr = (r >> 4) * HH + js * 16 + (r & 15);
        wih_s[r * 52 + k] = Wih[(size_t)gr * 51 + k];
    }
    for (int i = tid; i < OUTF * 16; i += NTHR) {
        int o = i >> 4, jl = i & 15;
        wout_s[i] = Wout[(size_t)o * HH + js * 16 + jl];
    }
    if (tid < 16) whalt_s[tid] = Whalt[js * 16 + tid];
    if (tid < 128) { cs[tid] = 0.f; accc[tid] = 0.f; }
    for (int i = tid; i < 528; i += NTHR) accy[i] = 0.f;
    if (tid < 8) { cum_s[tid] = 0.f; nupd_s[tid] = 0.f; rem_s[tid] = 0.f; done_s[tid] = 0; }
    for (int i = tid; i < GB * NIN; i += NTHR) {
        int bb = i / NIN, k = i - bb * NIN;
        x_sh[bb * 52 + k] = x[((size_t)(bgbase + bb) * TT) * NIN + k];
    }
    __syncthreads();

    const float brow  = bias[grow];
    const float flagw = wih_s[rowl * 52 + 50];   // ACT first-step flag column
    float gx0;
    {
        float s = brow;
        #pragma unroll
        for (int k = 0; k < NIN; k++) s += x_sh[bl * 52 + k] * wih_s[rowl * 52 + k];
        gx0 = s;
    }

    unsigned lgen = 0;
    int ns_prev = 0;          // ponder steps of previous timestep
    int tp = 0;               // t parity for g_hstep

    // ================= time loop =================
    for (int t = 0; t < TT; t++) {
        const int pp = tp ^ 1;
        int nlast = 0;

        for (int n = 0; n < MAXP; n++) {
            // ---- stage h input (n==0: reconstruct weighted h from prev timestep) ----
            if (n == 0) {
                for (int idx = tid; idx < GB * HH; idx += NTHR) {
                    int bb = idx >> 9, k = idx & 511;
                    float v = 0.f;
                    for (int m = 0; m < ns_prev; m++)
                        v += p_hist[m][bb] * g_hstep[pp][m][bgbase + bb][k];
                    h_sh[bb * 516 + k] = v;
                }
            } else {
                for (int idx = tid; idx < GB * HH; idx += NTHR) {
                    int bb = idx >> 9, k = idx & 511;
                    h_sh[bb * 516 + k] = g_hstep[tp][n - 1][bgbase + bb][k];
                }
            }
            __syncthreads();

            // ---- gate GEMM (SMEM x SMEM, conflict-free, K=512) ----
            {
                const float4* w0 = reinterpret_cast<const float4*>(whh_s + rowl * 520);
                const float4* w1 = reinterpret_cast<const float4*>(whh_s + rowl * 520 + 260);
                const float4* h0 = reinterpret_cast<const float4*>(h_sh + bl * 516);
                const float4* h1 = reinterpret_cast<const float4*>(h_sh + bl * 516 + 256);
                float a0 = 0.f, a1 = 0.f, a2 = 0.f, a3 = 0.f;
                #pragma unroll 8
                for (int k4 = 0; k4 < 64; k4++) {
                    float4 w = w0[k4], h = h0[k4];
                    a0 += w.x * h.x; a1 += w.y * h.y; a2 += w.z * h.z; a3 += w.w * h.w;
                }
                #pragma unroll 8
                for (int k4 = 0; k4 < 64; k4++) {
                    float4 w = w1[k4], h = h1[k4];
                    a0 += w.x * h.x; a1 += w.y * h.y; a2 += w.z * h.z; a3 += w.w * h.w;
                }
                gate_sh[tid] = gx0 + (n == 0 ? flagw : 0.f) + ((a0 + a1) + (a2 + a3));
            }
            __syncthreads();

            // ---- pointwise LSTM cell (16 j x 8 b) ----
            if (tid < 128) {
                float gi = gate_sh[tid],       gf = gate_sh[128 + tid],
                      gg = gate_sh[256 + tid], go = gate_sh[384 + tid];
                float c2 = sigm(gf) * cs[tid] + sigm(gi) * tanhf(gg);
                float h2 = sigm(go) * tanhf(c2);
                cs[tid] = c2; h2s[tid] = h2;
                int jl = tid >> 3, bb = tid & 7;
                g_hstep[tp][n][bgbase + bb][js * 16 + jl] = h2;
                hw[tid] = h2 * whalt_s[jl];
            }
            __syncthreads();
            if (tid < 8) {
                float s = 0.f;
                #pragma unroll
                for (int q = 0; q < 16; q++) s += hw[q * 8 + tid];
                g_haltp[n & 1][js][bgbase + tid] = s;
            }
            // ---- y partial (pre-p) from this CTA's j-slice ----
            for (int idx = tid; idx < 528; idx += NTHR) {
                int o = idx >> 3, bb = idx & 7;
                float s = 0.f;
                #pragma unroll
                for (int jl = 0; jl < 16; jl++) s += h2s[jl * 8 + bb] * wout_s[o * 16 + jl];
                ypre[idx] = s;
            }

            bar_bg(bg, lgen);   // ONE barrier per ponder step

            // ---- ACT scalar update (replicated identically in all group CTAs) ----
            if (tid < 8) {
                float hd = 0.f;
                #pragma unroll 8
                for (int j2 = 0; j2 < NJS; j2++) hd += g_haltp[n & 1][j2][bgbase + tid];
                float halt   = sigm(hd + bhalt);
                int wasdone  = done_s[tid];
                int halted   = ((cum_s[tid] + halt) > 0.99f) || (n == MAXP - 1);
                float p      = wasdone ? 0.f : (halted ? (1.f - cum_s[tid]) : halt);
                nupd_s[tid] += wasdone ? 0.f : 1.f;
                rem_s[tid]  += (wasdone || !halted) ? 0.f : (1.f - cum_s[tid]);
                cum_s[tid]  += wasdone ? 0.f : halt;
                int dnew     = wasdone || halted;
                done_s[tid]  = dnew;
                p_s[tid] = p; p_hist[n][tid] = p;
                int all = __all_sync(0x000000FFu, dnew);
                if (tid == 0) alldone_sh = all;
            }
            __syncthreads();
            // ---- weighted accumulation (c local; y local partial) ----
            if (tid < 128) accc[tid] += p_s[tid & 7] * cs[tid];
            for (int idx = tid; idx < 528; idx += NTHR)
                accy[idx] += p_s[idx & 7] * ypre[idx];
            __syncthreads();

            nlast = n;
            if (alldone_sh) break;   // exact: all further contributions are zero
        }
        ns_prev = nlast + 1;

        // ---------- timestep transition (NO barrier) ----------
        if (tid < 128) { cs[tid] = accc[tid]; accc[tid] = 0.f; }
        for (int idx = tid; idx < 528; idx += NTHR) {
            int o = idx >> 3, bb = idx & 7;
            atomicAdd(&g_yacc[((size_t)(bgbase + bb) * TT + t) * OUTF + o], accy[idx]);
            accy[idx] = 0.f;
        }
        if (js == 0 && tid < 8)
            pout[(size_t)(bgbase + tid) * TT + t] = nupd_s[tid] + rem_s[tid];
        if (tid < 8) { cum_s[tid] = 0.f; nupd_s[tid] = 0.f; rem_s[tid] = 0.f; done_s[tid] = 0; }
        if (t + 1 < TT) {
            for (int i = tid; i < GB * NIN; i += NTHR) {
                int bb = i / NIN, k = i - bb * NIN;
                x_sh[bb * 52 + k] = x[((size_t)(bgbase + bb) * TT + (t + 1)) * NIN + k];
            }
        }
        __syncthreads();
        if (t + 1 < TT) {
            float s = brow;
            #pragma unroll
            for (int k = 0; k < NIN; k++) s += x_sh[bl * 52 + k] * wih_s[rowl * 52 + k];
            gx0 = s;
        }
        tp ^= 1;
    }

    // ---------------- exit: reset barrier state for the next graph replay ----------------
    __syncthreads();
    if (tid == 0) {
        __threadfence();
        unsigned a = atomicAdd(&g_exitcnt[bg * 32], 1u);
        if (a == 31u) {
            atomicExch(&g_exitcnt[bg * 32], 0u);
            atomicExch(&g_barcnt[bg * 32], 0u);
            atomicExch(&g_barflag[bg * 32], 0u);
        }
    }
}

// ---------------- aux kernels ----------------
__global__ void zero_yacc_kernel() {
    int i = blockIdx.x * blockDim.x + threadIdx.x;
    if (i < NB * TT * OUTF) g_yacc[i] = 0.f;
}

__global__ void softmax_kernel(const float* __restrict__ bout, float* __restrict__ out) {
    int bt  = blockIdx.x;        // b*TT + t
    int tid = threadIdx.x;       // 96 threads
    __shared__ float v[OUTF];
    __shared__ float mm[6], ss[6];
    if (tid < OUTF) v[tid] = g_yacc[(size_t)bt * OUTF + tid] + bout[tid];
    __syncthreads();
    if (tid < 6) {
        float m = -1e30f;
        #pragma unroll
        for (int q = 0; q < 11; q++) m = fmaxf(m, v[tid * 11 + q]);
        float s = 0.f;
        #pragma unroll
        for (int q = 0; q < 11; q++) s += expf(v[tid * 11 + q] - m);
        mm[tid] = m; ss[tid] = s;
    }
    __syncthreads();
    if (tid < OUTF) {
        int d = tid / 11;
        out[(size_t)bt * OUTF + tid] = expf(v[tid] - mm[d]) / ss[d];
    }
}

extern "C" void kernel_launch(void* const* d_in, const int* in_sizes, int n_in,
                              void* d_out, int out_size) {
    const float* x     = (const float*)d_in[0];
    const float* Wih   = (const float*)d_in[1];
    const float* Whh   = (const float*)d_in[2];
    const float* b     = (const float*)d_in[3];
    const float* Wout  = (const float*)d_in[4];
    const float* bout  = (const float*)d_in[5];
    const float* Whalt = (const float*)d_in[6];
    const float* bhalt = (const float*)d_in[7];
    float* out  = (float*)d_out;
    float* pout = out + (size_t)NB * TT * OUTF;

    cudaFuncSetAttribute(act_lstm_main, cudaFuncAttributeMaxDynamicSharedMemorySize,
                         DSM_FLOATS * 4);

    zero_yacc_kernel<<<(NB * TT * OUTF + 1023) / 1024, 1024>>>();
    act_lstm_main<<<NCTA, NTHR, DSM_FLOATS * 4>>>(x, Wih, Whh, b, Wout, Whalt, bhalt, pout);
    softmax_kernel<<<NB * TT, 96>>>(bout, out);
}

// round 10
// speedup vs baseline: 1.8688x; 1.4751x over previous
#include <cuda_runtime.h>
#include <math.h>
#include <stdint.h>

#define NB    32
#define TT    512
#define NIN   50
#define HH    512
#define OUTF  66
#define MAXP  10
#define NJS   32      // CTAs per batch group
#define NBG   4       // independent batch groups
#define GB    8       // batches per group
#define NTHR  512
#define NCTA  128
#define PAD   516     // row pad: 516 mod 32 = 4 -> conflict-free f4 tiling

// ---------------- persistent device scratch (allocation-free) ----------------
__device__ float    g_hstep[2][MAXP][NB][HH];      // per-(t-parity, n) h2
__device__ float    g_haltp[2][MAXP][NJS][NB];     // halt-dot partials
__device__ float    g_yacc[NB * TT * OUTF];        // pre-softmax logits (atomic acc)
__device__ unsigned g_slot[NBG][NJS][32];          // distributed-barrier slots (128B apart)
__device__ unsigned g_exitcnt[NBG * 32];

__device__ __forceinline__ float sigm(float v) { return 1.0f / (1.0f + __expf(-v)); }
__device__ __forceinline__ void ffma2(unsigned long long& d, unsigned long long a,
                                      unsigned long long b) {
    asm("fma.rn.f32x2 %0, %1, %2, %0;" : "+l"(d) : "l"(a), "l"(b));
}
__device__ __forceinline__ float2 unpk(unsigned long long v) {
    float2 r; asm("mov.b64 {%0, %1}, %2;" : "=f"(r.x), "=f"(r.y) : "l"(v)); return r;
}
// volatile-strength L2 load/store for the barrier flag: the "memory" clobber +
// volatile keep these inside spin loops (a plain __ldcg gets LICM'd out -> hang,
// which is exactly what R9 hit).
__device__ __forceinline__ unsigned ldcg_poll(const unsigned* p) {
    unsigned v;
    asm volatile("ld.global.cg.u32 %0, [%1];" : "=r"(v) : "l"(p) : "memory");
    return v;
}
__device__ __forceinline__ void stcg_flag(unsigned* p, unsigned v) {
    asm volatile("st.global.cg.u32 [%0], %1;" :: "l"(p), "r"(v) : "memory");
}

// dynamic smem layout (float offsets)
#define WHH_OFF    0                       // [64][PAD]
#define WIH_OFF    (64 * PAD)              // [64][52]
#define WOUT_OFF   (WIH_OFF + 64 * 52)     // [66][16]
#define WHALT_OFF  (WOUT_OFF + 66 * 16)    // [16]
#define H_OFF      (WHALT_OFF + 16)        // [8][PAD] (16B aligned)
#define GX_OFF     (H_OFF + 8 * PAD)       // [512]
#define DSM_FLOATS (GX_OFF + 512)          // 42064 floats = 168256 B

extern __shared__ float dsm[];

__global__ void __launch_bounds__(NTHR, 1)
act_lstm_main(const float* __restrict__ x,       // [32,512,50]
              const float* __restrict__ Wih,     // [2048,51]
              const float* __restrict__ Whh,     // [2048,512]
              const float* __restrict__ bias,    // [2048]
              const float* __restrict__ Wout,    // [66,512]
              const float* __restrict__ Whalt,   // [512]
              const float* __restrict__ bhaltp,  // [1]
              float* __restrict__ pout)          // ponder-cost region of d_out
{
    const int bg     = blockIdx.x >> 5;
    const int js     = blockIdx.x & 31;
    const int bgbase = bg * GB;
    const int tid    = threadIdx.x;
    const int rowl   = tid >> 3;                 // 0..63 local gate row (gx map)
    const int bl8    = tid & 7;                  // batch-in-group
    const int grow   = (rowl >> 4) * HH + js * 16 + (rowl & 15);
    const float bhalt = bhaltp[0];

    float* whh_s   = dsm + WHH_OFF;
    float* wih_s   = dsm + WIH_OFF;
    float* wout_s  = dsm + WOUT_OFF;
    float* whalt_s = dsm + WHALT_OFF;
    float* h_sh    = dsm + H_OFF;
    float* gx_sh   = dsm + GX_OFF;

    __shared__ float gate_sh[512];
    __shared__ float h2s[128], cs[128], accc[128];
    __shared__ float accy[528], ypre[528];
    __shared__ float hw[128];
    __shared__ float hp_red[256];
    __shared__ float x_sh[GB * 52];
    __shared__ float p_hist[MAXP][8];
    __shared__ float cum_s[8], nupd_s[8], rem_s[8], p_s[8];
    __shared__ int   done_s[8], alldone_sh;

    // ---------------- prologue ----------------
    for (int f4 = tid; f4 < 64 * 128; f4 += NTHR) {
        int r = f4 >> 7, kk = (f4 & 127) << 2;
        int gr = (r >> 4) * HH + js * 16 + (r & 15);
        float4 w = *reinterpret_cast<const float4*>(Whh + (size_t)gr * HH + kk);
        *reinterpret_cast<float4*>(whh_s + r * PAD + kk) = w;
    }
    for (int i = tid; i < 64 * 51; i += NTHR) {
        int r = i / 51, k = i - r * 51;
        int gr = (r >> 4) * HH + js * 16 + (r & 15);
        wih_s[r * 52 + k] = Wih[(size_t)gr * 51 + k];
    }
    for (int i = tid; i < OUTF * 16; i += NTHR) {
        int o = i >> 4, jl = i & 15;
        wout_s[i] = Wout[(size_t)o * HH + js * 16 + jl];
    }
    if (tid < 16) whalt_s[tid] = Whalt[js * 16 + tid];
    // zero this CTA's share of the group's y accumulator; ordered before any
    // group atomicAdd by the first group barrier's release fence
    {
        const int chunk = GB * TT * OUTF / NJS;     // 8448
        float* base = g_yacc + (size_t)bgbase * TT * OUTF + (size_t)js * chunk;
        for (int i = tid; i < chunk; i += NTHR) __stcg(base + i, 0.0f);
    }
    #pragma unroll
    for (int i = 0; i < 8; i++) h_sh[i * PAD + tid] = 0.0f;
    if (tid < 128) { cs[tid] = 0.f; accc[tid] = 0.f; }
    for (int i = tid; i < 528; i += NTHR) accy[i] = 0.f;
    if (tid < 8) { cum_s[tid] = 0.f; nupd_s[tid] = 0.f; rem_s[tid] = 0.f; done_s[tid] = 0; }
    for (int i = tid; i < GB * NIN; i += NTHR) {
        int bb = i / NIN, k = i - bb * NIN;
        x_sh[bb * 52 + k] = x[((size_t)(bgbase + bb) * TT) * NIN + k];
    }
    __syncthreads();

    const float brow = bias[grow];
    {   // gx for t=0
        float s = brow;
        #pragma unroll
        for (int k = 0; k < NIN; k++) s += x_sh[bl8 * 52 + k] * wih_s[rowl * 52 + k];
        gx_sh[rowl * 8 + bl8] = s;
    }
    __syncthreads();

    unsigned lgen = 0;
    int tp = 0;

    // ================= time loop =================
    for (int t = 0; t < TT; t++) {
        int nlast = 0;
        float hreg[8];

        for (int n = 0; n < MAXP; n++) {
            // ---- gate GEMM: 256 threads, 2 rows x 1 batch each, f32x2 FMA ----
            if (tid < 256) {
                const int rp = tid >> 3, bl = tid & 7;
                const int r0 = rp * 2, r1 = r0 + 1;
                const ulonglong2* __restrict__ w0 =
                    reinterpret_cast<const ulonglong2*>(whh_s + r0 * PAD);
                const ulonglong2* __restrict__ w1 =
                    reinterpret_cast<const ulonglong2*>(whh_s + r1 * PAD);
                const ulonglong2* __restrict__ hp =
                    reinterpret_cast<const ulonglong2*>(h_sh + bl * PAD);
                unsigned long long a00 = 0ull, a01 = 0ull, a10 = 0ull, a11 = 0ull;
                #pragma unroll 8
                for (int k = 0; k < 128; k++) {
                    ulonglong2 hv = hp[k];
                    ulonglong2 wa = w0[k];
                    ulonglong2 wb = w1[k];
                    ffma2(a00, wa.x, hv.x); ffma2(a01, wa.y, hv.y);
                    ffma2(a10, wb.x, hv.x); ffma2(a11, wb.y, hv.y);
                }
                float2 u0 = unpk(a00), u1 = unpk(a01), u2 = unpk(a10), u3 = unpk(a11);
                gate_sh[r0 * 8 + bl] = (u0.x + u0.y) + (u1.x + u1.y);
                gate_sh[r1 * 8 + bl] = (u2.x + u2.y) + (u3.x + u3.y);
            }
            __syncthreads();

            // ---- pointwise LSTM cell (16 j x 8 b) ----
            if (tid < 128) {
                const int jl = tid >> 3, bl = tid & 7;
                const float fl = (n == 0) ? 1.0f : 0.0f;
                float gi = gate_sh[jl * 8 + bl]        + gx_sh[jl * 8 + bl]
                         + fl * wih_s[jl * 52 + 50];
                float gf = gate_sh[(16 + jl) * 8 + bl] + gx_sh[(16 + jl) * 8 + bl]
                         + fl * wih_s[(16 + jl) * 52 + 50];
                float gg = gate_sh[(32 + jl) * 8 + bl] + gx_sh[(32 + jl) * 8 + bl]
                         + fl * wih_s[(32 + jl) * 52 + 50];
                float go = gate_sh[(48 + jl) * 8 + bl] + gx_sh[(48 + jl) * 8 + bl]
                         + fl * wih_s[(48 + jl) * 52 + 50];
                float c2 = sigm(gf) * cs[tid] + sigm(gi) * tanhf(gg);
                float h2 = sigm(go) * tanhf(c2);
                cs[tid] = c2; h2s[tid] = h2;
                __stcg(&g_hstep[tp][n][bgbase + bl][js * 16 + jl], h2);
                hw[tid] = h2 * whalt_s[jl];
            }
            __syncthreads();
            if (tid < 8) {
                float s = 0.f;
                #pragma unroll
                for (int q = 0; q < 16; q++) s += hw[q * 8 + tid];
                __stcg(&g_haltp[tp][n][js][bgbase + tid], s);
            }
            __syncthreads();

            // ---- distributed barrier: arrive (stcg) / wait (volatile ldcg poll) ----
            if (tid == 0) {
                __threadfence();                         // release: data drained to L2
                stcg_flag(&g_slot[bg][js][0], lgen + 1);
            }
            if (tid >= 32) {                             // overlap: y partials
                for (int idx = tid - 32; idx < 528; idx += NTHR - 32) {
                    int o = idx >> 3, bb = idx & 7;
                    float s = 0.f;
                    #pragma unroll
                    for (int jl = 0; jl < 16; jl++)
                        s += h2s[jl * 8 + bb] * wout_s[o * 16 + jl];
                    ypre[idx] = s;
                }
            } else {
                const unsigned tgt = lgen + 1;
                for (;;) {
                    unsigned v = ldcg_poll(&g_slot[bg][tid][0]);
                    if (__all_sync(0xffffffffu, v >= tgt)) break;
                    __nanosleep(20);
                }
            }
            __syncthreads();
            lgen++;

            // ---- post-barrier: parallel halt loads + next-h loads ----
            #pragma unroll
            for (int i = 0; i < 8; i++)
                hreg[i] = __ldcg(&g_hstep[tp][n][bgbase + i][tid]);
            if (tid < 256)
                hp_red[tid] = __ldcg(&g_haltp[tp][n][tid >> 3][bgbase + (tid & 7)]);
            __syncthreads();

            // ---- ACT scalars (replicated identically in all group CTAs) ----
            if (tid < 8) {
                float hd = 0.f;
                #pragma unroll
                for (int q = 0; q < 32; q++) hd += hp_red[q * 8 + tid];
                float halt  = sigm(hd + bhalt);
                int wasdone = done_s[tid];
                int halted  = ((cum_s[tid] + halt) > 0.99f) || (n == MAXP - 1);
                float p     = wasdone ? 0.f : (halted ? (1.f - cum_s[tid]) : halt);
                nupd_s[tid] += wasdone ? 0.f : 1.f;
                rem_s[tid]  += (wasdone || !halted) ? 0.f : (1.f - cum_s[tid]);
                cum_s[tid]  += wasdone ? 0.f : halt;
                int dnew = wasdone || halted;
                done_s[tid] = dnew;
                p_s[tid] = p; p_hist[n][tid] = p;
                int all = __all_sync(0x000000FFu, dnew);
                if (tid == 0) alldone_sh = all;
            }
            __syncthreads();

            // ---- stage next h + weighted accumulation ----
            if (!alldone_sh) {
                #pragma unroll
                for (int i = 0; i < 8; i++) h_sh[i * PAD + tid] = hreg[i];
            }
            if (tid < 128) accc[tid] += p_s[tid & 7] * cs[tid];
            for (int idx = tid; idx < 528; idx += NTHR)
                accy[idx] += p_s[idx & 7] * ypre[idx];
            __syncthreads();

            nlast = n;
            if (alldone_sh) break;
        }

        // ---------- timestep transition (no barrier) ----------
        const int tp_old = tp;
        if (t + 1 < TT) {
            // reconstruct weighted h for t+1 (hreg already holds h_{nlast})
            #pragma unroll
            for (int i = 0; i < 8; i++) {
                float v = p_hist[nlast][i] * hreg[i];
                for (int m = 0; m < nlast; m++)
                    v += p_hist[m][i] * __ldcg(&g_hstep[tp_old][m][bgbase + i][tid]);
                h_sh[i * PAD + tid] = v;
            }
        }
        if (tid < 128) { cs[tid] = accc[tid]; accc[tid] = 0.f; }
        for (int idx = tid; idx < 528; idx += NTHR) {
            int o = idx >> 3, bb = idx & 7;
            atomicAdd(&g_yacc[((size_t)(bgbase + bb) * TT + t) * OUTF + o], accy[idx]);
            accy[idx] = 0.f;
        }
        if (js == 0 && tid < 8)
            pout[(size_t)(bgbase + tid) * TT + t] = nupd_s[tid] + rem_s[tid];
        if (tid < 8) { cum_s[tid] = 0.f; nupd_s[tid] = 0.f; rem_s[tid] = 0.f; done_s[tid] = 0; }
        if (t + 1 < TT) {
            for (int i = tid; i < GB * NIN; i += NTHR) {
                int bb = i / NIN, k = i - bb * NIN;
                x_sh[bb * 52 + k] = x[((size_t)(bgbase + bb) * TT + (t + 1)) * NIN + k];
            }
        }
        __syncthreads();
        if (t + 1 < TT) {
            float s = brow;
            #pragma unroll
            for (int k = 0; k < NIN; k++) s += x_sh[bl8 * 52 + k] * wih_s[rowl * 52 + k];
            gx_sh[rowl * 8 + bl8] = s;
        }
        tp ^= 1;
        __syncthreads();
    }

    // ---------------- exit: reset barrier slots for the next graph replay ----------------
    __syncthreads();
    if (tid == 0) {
        __threadfence();
        unsigned a = atomicAdd(&g_exitcnt[bg * 32], 1u);
        if (a == 31u) {                      // last exiter of the group
            atomicExch(&g_exitcnt[bg * 32], 0u);
            for (int q = 0; q < NJS; q++) atomicExch(&g_slot[bg][q][0], 0u);
        }
    }
}

// ---------------- aux kernels ----------------
__global__ void softmax_kernel(const float* __restrict__ bout, float* __restrict__ out) {
    int bt  = blockIdx.x;
    int tid = threadIdx.x;
    __shared__ float v[OUTF];
    __shared__ float mm[6], ss[6];
    if (tid < OUTF) v[tid] = __ldcg(&g_yacc[(size_t)bt * OUTF + tid]) + bout[tid];
    __syncthreads();
    if (tid < 6) {
        float m = -1e30f;
        #pragma unroll
        for (int q = 0; q < 11; q++) m = fmaxf(m, v[tid * 11 + q]);
        float s = 0.f;
        #pragma unroll
        for (int q = 0; q < 11; q++) s += expf(v[tid * 11 + q] - m);
        mm[tid] = m; ss[tid] = s;
    }
    __syncthreads();
    if (tid < OUTF) {
        int d = tid / 11;
        out[(size_t)bt * OUTF + tid] = expf(v[tid] - mm[d]) / ss[d];
    }
}

__global__ void dummy_kernel() {}   // launch-slot spacers so ncu (-s 5 -c 1) lands on main

extern "C" void kernel_launch(void* const* d_in, const int* in_sizes, int n_in,
                              void* d_out, int out_size) {
    const float* x     = (const float*)d_in[0];
    const float* Wih   = (const float*)d_in[1];
    const float* Whh   = (const float*)d_in[2];
    const float* b     = (const float*)d_in[3];
    const float* Wout  = (const float*)d_in[4];
    const float* bout  = (const float*)d_in[5];
    const float* Whalt = (const float*)d_in[6];
    const float* bhalt = (const float*)d_in[7];
    float* out  = (float*)d_out;
    float* pout = out + (size_t)NB * TT * OUTF;

    cudaFuncSetAttribute(act_lstm_main, cudaFuncAttributeMaxDynamicSharedMemorySize,
                         DSM_FLOATS * 4);

    dummy_kernel<<<1, 32>>>();
    act_lstm_main<<<NCTA, NTHR, DSM_FLOATS * 4>>>(x, Wih, Whh, b, Wout, Whalt, bhalt, pout);
    softmax_kernel<<<NB * TT, 96>>>(bout, out);
    dummy_kernel<<<1, 32>>>();
}

// round 13
// speedup vs baseline: 1.9069x; 1.0204x over previous
#include <cuda_runtime.h>
#include <math.h>
#include <stdint.h>

#define NB    32
#define TT    512
#define NIN   50
#define HH    512
#define OUTF  66
#define MAXP  10
#define NJS   32      // CTAs per batch group
#define NBG   4       // independent batch groups
#define GB    8       // batches per group
#define NTHR  512
#define NCTA  128
#define PAD   516     // row pad: 516 mod 32 = 4 -> conflict-free f4 tiling

// ---------------- persistent device scratch (allocation-free) ----------------
__device__ float    g_hstep[2][NBG][HH][GB];     // n-parity buffered h2 exchange, [j][b] coalesced
__device__ float    g_haltp[2][NBG][NJS][GB];    // n-parity halt-dot partials
__device__ float    g_yacc[NB * TT * OUTF];      // pre-softmax logits (RED accumulate)
__device__ unsigned g_slot[NBG][NJS][32];        // distributed-barrier slots (128B apart)
__device__ unsigned g_exitcnt[NBG * 32];

__device__ __forceinline__ float sigm(float v) { return 1.0f / (1.0f + __expf(-v)); }
__device__ __forceinline__ void ffma2(unsigned long long& d, unsigned long long a,
                                      unsigned long long b) {
    asm("fma.rn.f32x2 %0, %1, %2, %0;" : "+l"(d) : "l"(a), "l"(b));
}
__device__ __forceinline__ float2 unpk(unsigned long long v) {
    float2 r; asm("mov.b64 {%0, %1}, %2;" : "=f"(r.x), "=f"(r.y) : "l"(v)); return r;
}
// volatile-strength L2 flag ops: asm volatile + "memory" clobber keeps them inside
// spin loops (plain __ldcg gets LICM'd out -> hang; R9 lesson).
__device__ __forceinline__ unsigned ldcg_poll(const unsigned* p) {
    unsigned v;
    asm volatile("ld.global.cg.u32 %0, [%1];" : "=r"(v) : "l"(p) : "memory");
    return v;
}
__device__ __forceinline__ void stcg_flag(unsigned* p, unsigned v) {
    asm volatile("st.global.cg.u32 [%0], %1;" :: "l"(p), "r"(v) : "memory");
}

// dynamic smem layout (float offsets)
#define WHH_OFF    0                       // [64][PAD]
#define WIH_OFF    (64 * PAD)              // [64][52]
#define WOUT_OFF   (WIH_OFF + 64 * 52)     // [66][16]
#define WHALT_OFF  (WOUT_OFF + 66 * 16)    // [16]
#define H_OFF      (WHALT_OFF + 16)        // [8][PAD] (16B aligned)
#define GX_OFF     (H_OFF + 8 * PAD)       // [512]
#define DSM_FLOATS (GX_OFF + 512)          // 42064 floats = 168256 B

extern __shared__ float dsm[];

__global__ void __launch_bounds__(NTHR, 1)
act_lstm_main(const float* __restrict__ x,       // [32,512,50]
              const float* __restrict__ Wih,     // [2048,51]
              const float* __restrict__ Whh,     // [2048,512]
              const float* __restrict__ bias,    // [2048]
              const float* __restrict__ Wout,    // [66,512]
              const float* __restrict__ bout,    // [66]
              const float* __restrict__ Whalt,   // [512]
              const float* __restrict__ bhaltp,  // [1]
              float* __restrict__ out)           // [32*512*66] ++ [32*512] ponder
{
    const int bg     = blockIdx.x >> 5;
    const int js     = blockIdx.x & 31;
    const int bgbase = bg * GB;
    const int tid    = threadIdx.x;
    const int rowl   = tid >> 3;                 // 0..63 local gate row (gx map)
    const int bl8    = tid & 7;                  // batch-in-group
    const int grow   = (rowl >> 4) * HH + js * 16 + (rowl & 15);
    const float bhalt = bhaltp[0];
    float* pout = out + (size_t)NB * TT * OUTF;

    float* whh_s   = dsm + WHH_OFF;
    float* wih_s   = dsm + WIH_OFF;
    float* wout_s  = dsm + WOUT_OFF;
    float* whalt_s = dsm + WHALT_OFF;
    float* h_sh    = dsm + H_OFF;
    float* gx_sh   = dsm + GX_OFF;

    __shared__ float gate_sh[512];
    __shared__ float h2s[128], cs[128], accc[128], acch[128];
    __shared__ float hp4[4][8];
    __shared__ float x_sh[GB * 52];
    __shared__ float boutsh[OUTF];
    __shared__ float cum_s[8], nupd_s[8], rem_s[8], p_s[8];
    __shared__ int   done_s[8], alldone_sh;
    __shared__ float vb[16][68];                 // 16 warps (R12 bug: was [8] -> OOB)
    __shared__ float msm[16][6], mss[16][6];

    // ---------------- prologue ----------------
    for (int f4 = tid; f4 < 64 * 128; f4 += NTHR) {
        int r = f4 >> 7, kk = (f4 & 127) << 2;
        int gr = (r >> 4) * HH + js * 16 + (r & 15);
        float4 w = *reinterpret_cast<const float4*>(Whh + (size_t)gr * HH + kk);
        *reinterpret_cast<float4*>(whh_s + r * PAD + kk) = w;
    }
    for (int i = tid; i < 64 * 51; i += NTHR) {
        int r = i / 51, k = i - r * 51;
        int gr = (r >> 4) * HH + js * 16 + (r & 15);
        wih_s[r * 52 + k] = Wih[(size_t)gr * 51 + k];
    }
    for (int i = tid; i < OUTF * 16; i += NTHR) {
        int o = i >> 4, jl = i & 15;
        wout_s[i] = Wout[(size_t)o * HH + js * 16 + jl];
    }
    if (tid < 16)   whalt_s[tid] = Whalt[js * 16 + tid];
    if (tid < OUTF) boutsh[tid]  = bout[tid];
    // zero this CTA's share of the group's y accumulator; drained to L2 before the
    // first group-barrier flag (release fence covers all CTA threads' stores via
    // syncthreads cumulativity), and peers RED only after observing that flag
    {
        const int chunk = GB * TT * OUTF / NJS;     // 8448
        float* base = g_yacc + (size_t)bgbase * TT * OUTF + (size_t)js * chunk;
        for (int i = tid; i < chunk; i += NTHR) __stcg(base + i, 0.0f);
    }
    #pragma unroll
    for (int i = 0; i < 8; i++) h_sh[i * PAD + tid] = 0.0f;   // h0 = 0
    if (tid < 128) { cs[tid] = 0.f; accc[tid] = 0.f; acch[tid] = 0.f; }
    if (tid < 8) { cum_s[tid] = 0.f; nupd_s[tid] = 0.f; rem_s[tid] = 0.f; done_s[tid] = 0; }
    for (int i = tid; i < GB * NIN; i += NTHR) {
        int bb = i / NIN, k = i - bb * NIN;
        x_sh[bb * 52 + k] = x[((size_t)(bgbase + bb) * TT) * NIN + k];
    }
    __syncthreads();

    const float brow = bias[grow];
    {   // gx for t=0
        float s = brow;
        #pragma unroll
        for (int k = 0; k < NIN; k++) s += x_sh[bl8 * 52 + k] * wih_s[rowl * 52 + k];
        gx_sh[rowl * 8 + bl8] = s;
    }
    __syncthreads();

    unsigned lgen = 0;
    float hacc0 = 0.f, hacc1 = 0.f, hacc2 = 0.f, hacc3 = 0.f;
    float hacc4 = 0.f, hacc5 = 0.f, hacc6 = 0.f, hacc7 = 0.f;

    // ================= time loop =================
    for (int t = 0; t < TT; t++) {
        for (int n = 0; n < MAXP; n++) {
            const int par = n & 1;

            // ---- gate GEMM: 256 threads, 2 rows x 1 batch, f32x2 FMA ----
            if (tid < 256) {
                const int rp = tid >> 3, bl = tid & 7;
                const int r0 = rp * 2, r1 = r0 + 1;
                const ulonglong2* __restrict__ w0 =
                    reinterpret_cast<const ulonglong2*>(whh_s + r0 * PAD);
                const ulonglong2* __restrict__ w1 =
                    reinterpret_cast<const ulonglong2*>(whh_s + r1 * PAD);
                const ulonglong2* __restrict__ hp =
                    reinterpret_cast<const ulonglong2*>(h_sh + bl * PAD);
                unsigned long long a00 = 0ull, a01 = 0ull, a10 = 0ull, a11 = 0ull;
                #pragma unroll 8
                for (int k = 0; k < 128; k++) {
                    ulonglong2 hv = hp[k];
                    ulonglong2 wa = w0[k];
                    ulonglong2 wb = w1[k];
                    ffma2(a00, wa.x, hv.x); ffma2(a01, wa.y, hv.y);
                    ffma2(a10, wb.x, hv.x); ffma2(a11, wb.y, hv.y);
                }
                float2 u0 = unpk(a00), u1 = unpk(a01), u2 = unpk(a10), u3 = unpk(a11);
                gate_sh[r0 * 8 + bl] = (u0.x + u0.y) + (u1.x + u1.y);
                gate_sh[r1 * 8 + bl] = (u2.x + u2.y) + (u3.x + u3.y);
            }
            __syncthreads();                                   // sync 1

            // ---- pointwise LSTM cell + halt partial (warp-shuffle) ----
            if (tid < 128) {
                const int jl = tid >> 3, bl = tid & 7;
                const float fl = (n == 0) ? 1.0f : 0.0f;
                float gi = gate_sh[jl * 8 + bl]        + gx_sh[jl * 8 + bl]
                         + fl * wih_s[jl * 52 + 50];
                float gf = gate_sh[(16 + jl) * 8 + bl] + gx_sh[(16 + jl) * 8 + bl]
                         + fl * wih_s[(16 + jl) * 52 + 50];
                float gg = gate_sh[(32 + jl) * 8 + bl] + gx_sh[(32 + jl) * 8 + bl]
                         + fl * wih_s[(32 + jl) * 52 + 50];
                float go = gate_sh[(48 + jl) * 8 + bl] + gx_sh[(48 + jl) * 8 + bl]
                         + fl * wih_s[(48 + jl) * 52 + 50];
                float c2 = sigm(gf) * cs[tid] + sigm(gi) * tanhf(gg);
                float h2 = sigm(go) * tanhf(c2);
                cs[tid] = c2; h2s[tid] = h2;
                // coalesced h2 publish within [HH][GB] layout
                __stcg(&g_hstep[par][bg][js * 16 + jl][bl], h2);
                float hwv = h2 * whalt_s[jl];
                hwv += __shfl_xor_sync(0xffffffffu, hwv, 8);
                hwv += __shfl_xor_sync(0xffffffffu, hwv, 16);
                if ((tid & 31) < 8) hp4[tid >> 5][tid & 7] = hwv;
            }
            __syncthreads();                                   // sync 2

            // ---- barrier: tid0 publishes haltp + flag; warp15 polls ----
            if (tid == 0) {
                #pragma unroll
                for (int b = 0; b < 8; b++) {
                    float s = hp4[0][b] + hp4[1][b] + hp4[2][b] + hp4[3][b];
                    __stcg(&g_haltp[par][bg][js][b], s);
                }
                __threadfence();                               // release to L2
                stcg_flag(&g_slot[bg][js][0], lgen + 1);
            } else if (tid >= 480) {
                const unsigned tgt = lgen + 1;
                for (;;) {
                    unsigned v = ldcg_poll(&g_slot[bg][tid & 31][0]);
                    if (__all_sync(0xffffffffu, v >= tgt)) break;
                    __nanosleep(32);
                }
            }
            __syncthreads();                                   // sync 3
            lgen++;

            // ---- merged load + ACT + stage ----
            float4 v0, v1;
            {
                const float* hb = &g_hstep[par][bg][0][0];
                v0 = __ldcg(reinterpret_cast<const float4*>(hb + tid * 8));
                v1 = __ldcg(reinterpret_cast<const float4*>(hb + tid * 8 + 4));
            }
            h_sh[0 * PAD + tid] = v0.x; h_sh[1 * PAD + tid] = v0.y;
            h_sh[2 * PAD + tid] = v0.z; h_sh[3 * PAD + tid] = v0.w;
            h_sh[4 * PAD + tid] = v1.x; h_sh[5 * PAD + tid] = v1.y;
            h_sh[6 * PAD + tid] = v1.z; h_sh[7 * PAD + tid] = v1.w;
            if (tid < 8) {
                float hd = 0.f;
                #pragma unroll 8
                for (int j2 = 0; j2 < NJS; j2++)
                    hd += __ldcg(&g_haltp[par][bg][j2][tid]);
                float halt  = sigm(hd + bhalt);
                int wasdone = done_s[tid];
                int halted  = ((cum_s[tid] + halt) > 0.99f) || (n == MAXP - 1);
                float p     = wasdone ? 0.f : (halted ? (1.f - cum_s[tid]) : halt);
                nupd_s[tid] += wasdone ? 0.f : 1.f;
                rem_s[tid]  += (wasdone || !halted) ? 0.f : (1.f - cum_s[tid]);
                cum_s[tid]  += wasdone ? 0.f : halt;
                int dnew = wasdone || halted;
                done_s[tid] = dnew;
                p_s[tid] = p;
                int all = __all_sync(0x000000FFu, dnew);
                if (tid == 0) alldone_sh = all;
            }
            __syncthreads();                                   // sync 4

            // ---- weighted accumulation (register hacc = full weighted h) ----
            hacc0 += p_s[0] * v0.x; hacc1 += p_s[1] * v0.y;
            hacc2 += p_s[2] * v0.z; hacc3 += p_s[3] * v0.w;
            hacc4 += p_s[4] * v1.x; hacc5 += p_s[5] * v1.y;
            hacc6 += p_s[6] * v1.z; hacc7 += p_s[7] * v1.w;
            if (tid < 128) {
                float p = p_s[tid & 7];
                accc[tid] += p * cs[tid];
                acch[tid] += p * h2s[tid];
            }
            if (alldone_sh) break;
        }

        // ---------- timestep transition ----------
        __syncthreads();   // T-sync-A: acch/accc complete before cross-thread reads
        // stage weighted h for t+1 directly from registers; reset
        h_sh[0 * PAD + tid] = hacc0; h_sh[1 * PAD + tid] = hacc1;
        h_sh[2 * PAD + tid] = hacc2; h_sh[3 * PAD + tid] = hacc3;
        h_sh[4 * PAD + tid] = hacc4; h_sh[5 * PAD + tid] = hacc5;
        h_sh[6 * PAD + tid] = hacc6; h_sh[7 * PAD + tid] = hacc7;
        hacc0 = hacc1 = hacc2 = hacc3 = hacc4 = hacc5 = hacc6 = hacc7 = 0.f;
        // y projection ONCE per timestep from local weighted-h slice (linearity)
        {
            int o = tid >> 3, bl = tid & 7;
            float s = 0.f;
            #pragma unroll
            for (int jl = 0; jl < 16; jl++) s += acch[jl * 8 + bl] * wout_s[o * 16 + jl];
            atomicAdd(&g_yacc[((size_t)(bgbase + bl) * TT + t) * OUTF + o], s);
            if (tid < 16) {
                int idx = 512 + tid, o2 = idx >> 3, bl2 = idx & 7;
                float s2 = 0.f;
                #pragma unroll
                for (int jl = 0; jl < 16; jl++) s2 += acch[jl * 8 + bl2] * wout_s[o2 * 16 + jl];
                atomicAdd(&g_yacc[((size_t)(bgbase + bl2) * TT + t) * OUTF + o2], s2);
            }
        }
        if (js == 0 && tid < 8)
            pout[(size_t)(bgbase + tid) * TT + t] = nupd_s[tid] + rem_s[tid];
        __syncthreads();   // T-sync-Y: all acch readers done before reset (R12 race fix)
        if (tid < 128) { cs[tid] = accc[tid]; accc[tid] = 0.f; acch[tid] = 0.f; }
        if (tid < 8) { cum_s[tid] = 0.f; nupd_s[tid] = 0.f; rem_s[tid] = 0.f; done_s[tid] = 0; }
        if (t + 1 < TT && tid < GB * NIN) {
            int bb = tid / NIN, k = tid - bb * NIN;
            x_sh[bb * 52 + k] = x[((size_t)(bgbase + bb) * TT + (t + 1)) * NIN + k];
        }
        __syncthreads();   // T-sync-B
        if (t + 1 < TT) {
            float s = brow;
            #pragma unroll
            for (int k = 0; k < NIN; k++) s += x_sh[bl8 * 52 + k] * wih_s[rowl * 52 + k];
            gx_sh[rowl * 8 + bl8] = s;   // consumed by pointwise, after next sync 1
        }
    }

    // ---------------- epilogue: group barrier, then fused softmax ----------------
    __syncthreads();
    if (tid == 0) {
        __threadfence();                                   // drain REDs
        stcg_flag(&g_slot[bg][js][0], lgen + 1);
    } else if (tid >= 480) {
        const unsigned tgt = lgen + 1;
        for (;;) {
            unsigned v = ldcg_poll(&g_slot[bg][tid & 31][0]);
            if (__all_sync(0xffffffffu, v >= tgt)) break;
            __nanosleep(32);
        }
    }
    __syncthreads();
    lgen++;

    {   // 16 warps x 8 (b,t) pairs per CTA (128 total = this CTA's share of 4096)
        const int w = tid >> 5, lane = tid & 31;
        for (int k = 0; k < 8; k++) {
            int q    = js * 128 + w * 8 + k;       // 0..4095 within group
            int bloc = q >> 9, tt = q & 511;
            size_t base = ((size_t)(bgbase + bloc) * TT + tt) * OUTF;
            vb[w][lane]      = __ldcg(&g_yacc[base + lane])      + boutsh[lane];
            vb[w][32 + lane] = __ldcg(&g_yacc[base + 32 + lane]) + boutsh[32 + lane];
            if (lane < 2)
                vb[w][64 + lane] = __ldcg(&g_yacc[base + 64 + lane]) + boutsh[64 + lane];
            __syncwarp();
            if (lane < 6) {
                float m = -1e30f;
                #pragma unroll
                for (int q2 = 0; q2 < 11; q2++) m = fmaxf(m, vb[w][lane * 11 + q2]);
                float s = 0.f;
                #pragma unroll
                for (int q2 = 0; q2 < 11; q2++) s += expf(vb[w][lane * 11 + q2] - m);
                msm[w][lane] = m; mss[w][lane] = s;
            }
            __syncwarp();
            {
                int d0 = lane / 11, d1 = (32 + lane) / 11;
                out[base + lane]      = expf(vb[w][lane]      - msm[w][d0]) / mss[w][d0];
                out[base + 32 + lane] = expf(vb[w][32 + lane] - msm[w][d1]) / mss[w][d1];
                if (lane < 2)
                    out[base + 64 + lane] = expf(vb[w][64 + lane] - msm[w][5]) / mss[w][5];
            }
            __syncwarp();
        }
    }

    // ---------------- exit: reset barrier slots for the next graph replay ----------------
    __syncthreads();
    if (tid == 0) {
        __threadfence();
        unsigned a = atomicAdd(&g_exitcnt[bg * 32], 1u);
        if (a == 31u) {
            atomicExch(&g_exitcnt[bg * 32], 0u);
            for (int q = 0; q < NJS; q++) atomicExch(&g_slot[bg][q][0], 0u);
        }
    }
}

extern "C" void kernel_launch(void* const* d_in, const int* in_sizes, int n_in,
                              void* d_out, int out_size) {
    const float* x     = (const float*)d_in[0];
    const float* Wih   = (const float*)d_in[1];
    const float* Whh   = (const float*)d_in[2];
    const float* b     = (const float*)d_in[3];
    const float* Wout  = (const float*)d_in[4];
    const float* bout  = (const float*)d_in[5];
    const float* Whalt = (const float*)d_in[6];
    const float* bhalt = (const float*)d_in[7];
    float* out = (float*)d_out;

    cudaFuncSetAttribute(act_lstm_main, cudaFuncAttributeMaxDynamicSharedMemorySize,
                         DSM_FLOATS * 4);
    act_lstm_main<<<NCTA, NTHR, DSM_FLOATS * 4>>>(x, Wih, Whh, b, Wout, bout,
                                                  Whalt, bhalt, out);
}

// round 14
// speedup vs baseline: 1.9251x; 1.0095x over previous
#include <cuda_runtime.h>
#include <math.h>
#include <stdint.h>

#define NB    32
#define TT    512
#define NIN   50
#define HH    512
#define OUTF  66
#define MAXP  10
#define NJS   32      // CTAs per batch group
#define NBG   4       // independent batch groups
#define GB    8       // batches per group
#define NTHR  512
#define NCTA  128
#define PAD   516     // row pad: 516 mod 32 = 4 -> conflict-free f4 tiling

// ---------------- persistent device scratch (allocation-free) ----------------
__device__ float    g_hstep[2][NBG][HH][GB];     // n-parity buffered h2 exchange, [j][b] coalesced
__device__ float    g_haltp[2][NBG][NJS][GB];    // n-parity halt-dot partials
__device__ float    g_yacc[NB * TT * OUTF];      // pre-softmax logits (RED accumulate)
__device__ unsigned g_slot[NBG][NJS][32];        // distributed-barrier slots (128B apart)
__device__ unsigned g_exitcnt[NBG * 32];

__device__ __forceinline__ float sigm(float v) { return 1.0f / (1.0f + __expf(-v)); }
__device__ __forceinline__ void ffma2(unsigned long long& d, unsigned long long a,
                                      unsigned long long b) {
    asm("fma.rn.f32x2 %0, %1, %2, %0;" : "+l"(d) : "l"(a), "l"(b));
}
__device__ __forceinline__ float2 unpk(unsigned long long v) {
    float2 r; asm("mov.b64 {%0, %1}, %2;" : "=f"(r.x), "=f"(r.y) : "l"(v)); return r;
}
// volatile-strength L2 flag ops: asm volatile + "memory" clobber keeps them inside
// spin loops (plain __ldcg gets LICM'd out -> hang; R9 lesson).
__device__ __forceinline__ unsigned ldcg_poll(const unsigned* p) {
    unsigned v;
    asm volatile("ld.global.cg.u32 %0, [%1];" : "=r"(v) : "l"(p) : "memory");
    return v;
}
__device__ __forceinline__ void stcg_flag(unsigned* p, unsigned v) {
    asm volatile("st.global.cg.u32 [%0], %1;" :: "l"(p), "r"(v) : "memory");
}

// dynamic smem layout (float offsets)
#define WHH_OFF    0                       // [64][PAD]
#define WIH_OFF    (64 * PAD)              // [64][52]
#define WOUT_OFF   (WIH_OFF + 64 * 52)     // [66][16]
#define WHALT_OFF  (WOUT_OFF + 66 * 16)    // [16]
#define H_OFF      (WHALT_OFF + 16)        // [8][PAD] (16B aligned)
#define GX_OFF     (H_OFF + 8 * PAD)       // [512]
#define DSM_FLOATS (GX_OFF + 512)          // 42064 floats = 168256 B

extern __shared__ float dsm[];

__global__ void __launch_bounds__(NTHR, 1)
act_lstm_main(const float* __restrict__ x,       // [32,512,50]
              const float* __restrict__ Wih,     // [2048,51]
              const float* __restrict__ Whh,     // [2048,512]
              const float* __restrict__ bias,    // [2048]
              const float* __restrict__ Wout,    // [66,512]
              const float* __restrict__ bout,    // [66]
              const float* __restrict__ Whalt,   // [512]
              const float* __restrict__ bhaltp,  // [1]
              float* __restrict__ out)           // [32*512*66] ++ [32*512] ponder
{
    const int bg     = blockIdx.x >> 5;
    const int js     = blockIdx.x & 31;
    const int bgbase = bg * GB;
    const int tid    = threadIdx.x;
    const int rowl   = tid >> 3;                 // 0..63 local gate row (gx map)
    const int bl8    = tid & 7;                  // batch-in-group
    const int grow   = (rowl >> 4) * HH + js * 16 + (rowl & 15);
    const float bhalt = bhaltp[0];
    float* pout = out + (size_t)NB * TT * OUTF;

    float* whh_s   = dsm + WHH_OFF;
    float* wih_s   = dsm + WIH_OFF;
    float* wout_s  = dsm + WOUT_OFF;
    float* whalt_s = dsm + WHALT_OFF;
    float* h_sh    = dsm + H_OFF;
    float* gx_sh   = dsm + GX_OFF;

    __shared__ float gate_sh[512];
    __shared__ float h2s[128], cs[128], accc[128], acch[128];
    __shared__ float hp4[4][8];
    __shared__ float x_sh[GB * 52];
    __shared__ float boutsh[OUTF];
    __shared__ float cum_s[8], nupd_s[8], rem_s[8], p_s[8];
    __shared__ int   done_s[8], alldone_sh;
    __shared__ float vb[16][68];                 // 16 warps (R12 bug: was [8] -> OOB)
    __shared__ float msm[16][6], mss[16][6];

    // ---------------- prologue ----------------
    for (int f4 = tid; f4 < 64 * 128; f4 += NTHR) {
        int r = f4 >> 7, kk = (f4 & 127) << 2;
        int gr = (r >> 4) * HH + js * 16 + (r & 15);
        float4 w = *reinterpret_cast<const float4*>(Whh + (size_t)gr * HH + kk);
        *reinterpret_cast<float4*>(whh_s + r * PAD + kk) = w;
    }
    for (int i = tid; i < 64 * 51; i += NTHR) {
        int r = i / 51, k = i - r * 51;
        int gr = (r >> 4) * HH + js * 16 + (r & 15);
        wih_s[r * 52 + k] = Wih[(size_t)gr * 51 + k];
    }
    for (int i = tid; i < OUTF * 16; i += NTHR) {
        int o = i >> 4, jl = i & 15;
        wout_s[i] = Wout[(size_t)o * HH + js * 16 + jl];
    }
    if (tid < 16)   whalt_s[tid] = Whalt[js * 16 + tid];
    if (tid < OUTF) boutsh[tid]  = bout[tid];
    // zero this CTA's share of the group's y accumulator; drained to L2 before the
    // first group-barrier flag (release fence covers all CTA threads' stores via
    // syncthreads cumulativity), and peers RED only after observing that flag
    {
        const int chunk = GB * TT * OUTF / NJS;     // 8448
        float* base = g_yacc + (size_t)bgbase * TT * OUTF + (size_t)js * chunk;
        for (int i = tid; i < chunk; i += NTHR) __stcg(base + i, 0.0f);
    }
    #pragma unroll
    for (int i = 0; i < 8; i++) h_sh[i * PAD + tid] = 0.0f;   // h0 = 0
    if (tid < 128) { cs[tid] = 0.f; accc[tid] = 0.f; acch[tid] = 0.f; }
    if (tid < 8) { cum_s[tid] = 0.f; nupd_s[tid] = 0.f; rem_s[tid] = 0.f; done_s[tid] = 0; }
    for (int i = tid; i < GB * NIN; i += NTHR) {
        int bb = i / NIN, k = i - bb * NIN;
        x_sh[bb * 52 + k] = x[((size_t)(bgbase + bb) * TT) * NIN + k];
    }
    __syncthreads();

    const float brow = bias[grow];
    {   // gx for t=0
        float s = brow;
        #pragma unroll
        for (int k = 0; k < NIN; k++) s += x_sh[bl8 * 52 + k] * wih_s[rowl * 52 + k];
        gx_sh[rowl * 8 + bl8] = s;
    }
    __syncthreads();

    unsigned lgen = 0;
    float hacc0 = 0.f, hacc1 = 0.f, hacc2 = 0.f, hacc3 = 0.f;
    float hacc4 = 0.f, hacc5 = 0.f, hacc6 = 0.f, hacc7 = 0.f;

    // ================= time loop =================
    for (int t = 0; t < TT; t++) {
        for (int n = 0; n < MAXP; n++) {
            const int par = n & 1;

            // ---- gate GEMM: 256 threads, 2 rows x 1 batch, f32x2 FMA ----
            if (tid < 256) {
                const int rp = tid >> 3, bl = tid & 7;
                const int r0 = rp * 2, r1 = r0 + 1;
                const ulonglong2* __restrict__ w0 =
                    reinterpret_cast<const ulonglong2*>(whh_s + r0 * PAD);
                const ulonglong2* __restrict__ w1 =
                    reinterpret_cast<const ulonglong2*>(whh_s + r1 * PAD);
                const ulonglong2* __restrict__ hp =
                    reinterpret_cast<const ulonglong2*>(h_sh + bl * PAD);
                unsigned long long a00 = 0ull, a01 = 0ull, a10 = 0ull, a11 = 0ull;
                #pragma unroll 8
                for (int k = 0; k < 128; k++) {
                    ulonglong2 hv = hp[k];
                    ulonglong2 wa = w0[k];
                    ulonglong2 wb = w1[k];
                    ffma2(a00, wa.x, hv.x); ffma2(a01, wa.y, hv.y);
                    ffma2(a10, wb.x, hv.x); ffma2(a11, wb.y, hv.y);
                }
                float2 u0 = unpk(a00), u1 = unpk(a01), u2 = unpk(a10), u3 = unpk(a11);
                gate_sh[r0 * 8 + bl] = (u0.x + u0.y) + (u1.x + u1.y);
                gate_sh[r1 * 8 + bl] = (u2.x + u2.y) + (u3.x + u3.y);
            }
            __syncthreads();                                   // sync 1

            // ---- pointwise LSTM cell + halt partial (warp-shuffle) ----
            if (tid < 128) {
                const int jl = tid >> 3, bl = tid & 7;
                const float fl = (n == 0) ? 1.0f : 0.0f;
                float gi = gate_sh[jl * 8 + bl]        + gx_sh[jl * 8 + bl]
                         + fl * wih_s[jl * 52 + 50];
                float gf = gate_sh[(16 + jl) * 8 + bl] + gx_sh[(16 + jl) * 8 + bl]
                         + fl * wih_s[(16 + jl) * 52 + 50];
                float gg = gate_sh[(32 + jl) * 8 + bl] + gx_sh[(32 + jl) * 8 + bl]
                         + fl * wih_s[(32 + jl) * 52 + 50];
                float go = gate_sh[(48 + jl) * 8 + bl] + gx_sh[(48 + jl) * 8 + bl]
                         + fl * wih_s[(48 + jl) * 52 + 50];
                float c2 = sigm(gf) * cs[tid] + sigm(gi) * tanhf(gg);
                float h2 = sigm(go) * tanhf(c2);
                cs[tid] = c2; h2s[tid] = h2;
                // coalesced h2 publish within [HH][GB] layout
                __stcg(&g_hstep[par][bg][js * 16 + jl][bl], h2);
                float hwv = h2 * whalt_s[jl];
                hwv += __shfl_xor_sync(0xffffffffu, hwv, 8);
                hwv += __shfl_xor_sync(0xffffffffu, hwv, 16);
                if ((tid & 31) < 8) hp4[tid >> 5][tid & 7] = hwv;
            }
            __syncthreads();                                   // sync 2

            // ---- barrier: tid0 publishes haltp + flag; warp15 polls ----
            if (tid == 0) {
                #pragma unroll
                for (int b = 0; b < 8; b++) {
                    float s = hp4[0][b] + hp4[1][b] + hp4[2][b] + hp4[3][b];
                    __stcg(&g_haltp[par][bg][js][b], s);
                }
                __threadfence();                               // release to L2
                stcg_flag(&g_slot[bg][js][0], lgen + 1);
            } else if (tid >= 480) {
                const unsigned tgt = lgen + 1;
                for (;;) {
                    unsigned v = ldcg_poll(&g_slot[bg][tid & 31][0]);
                    if (__all_sync(0xffffffffu, v >= tgt)) break;
                    __nanosleep(32);
                }
            }
            __syncthreads();                                   // sync 3
            lgen++;

            // ---- merged load + ACT + stage ----
            float4 v0, v1;
            {
                const float* hb = &g_hstep[par][bg][0][0];
                v0 = __ldcg(reinterpret_cast<const float4*>(hb + tid * 8));
                v1 = __ldcg(reinterpret_cast<const float4*>(hb + tid * 8 + 4));
            }
            h_sh[0 * PAD + tid] = v0.x; h_sh[1 * PAD + tid] = v0.y;
            h_sh[2 * PAD + tid] = v0.z; h_sh[3 * PAD + tid] = v0.w;
            h_sh[4 * PAD + tid] = v1.x; h_sh[5 * PAD + tid] = v1.y;
            h_sh[6 * PAD + tid] = v1.z; h_sh[7 * PAD + tid] = v1.w;
            if (tid < 8) {
                float hd = 0.f;
                #pragma unroll 8
                for (int j2 = 0; j2 < NJS; j2++)
                    hd += __ldcg(&g_haltp[par][bg][j2][tid]);
                float halt  = sigm(hd + bhalt);
                int wasdone = done_s[tid];
                int halted  = ((cum_s[tid] + halt) > 0.99f) || (n == MAXP - 1);
                float p     = wasdone ? 0.f : (halted ? (1.f - cum_s[tid]) : halt);
                nupd_s[tid] += wasdone ? 0.f : 1.f;
                rem_s[tid]  += (wasdone || !halted) ? 0.f : (1.f - cum_s[tid]);
                cum_s[tid]  += wasdone ? 0.f : halt;
                int dnew = wasdone || halted;
                done_s[tid] = dnew;
                p_s[tid] = p;
                int all = __all_sync(0x000000FFu, dnew);
                if (tid == 0) alldone_sh = all;
            }
            __syncthreads();                                   // sync 4

            // ---- weighted accumulation (register hacc = full weighted h) ----
            hacc0 += p_s[0] * v0.x; hacc1 += p_s[1] * v0.y;
            hacc2 += p_s[2] * v0.z; hacc3 += p_s[3] * v0.w;
            hacc4 += p_s[4] * v1.x; hacc5 += p_s[5] * v1.y;
            hacc6 += p_s[6] * v1.z; hacc7 += p_s[7] * v1.w;
            if (tid < 128) {
                float p = p_s[tid & 7];
                accc[tid] += p * cs[tid];
                acch[tid] += p * h2s[tid];
            }
            if (alldone_sh) break;
        }

        // ---------- timestep transition ----------
        __syncthreads();   // T-sync-A: acch/accc complete before cross-thread reads
        // stage weighted h for t+1 directly from registers; reset
        h_sh[0 * PAD + tid] = hacc0; h_sh[1 * PAD + tid] = hacc1;
        h_sh[2 * PAD + tid] = hacc2; h_sh[3 * PAD + tid] = hacc3;
        h_sh[4 * PAD + tid] = hacc4; h_sh[5 * PAD + tid] = hacc5;
        h_sh[6 * PAD + tid] = hacc6; h_sh[7 * PAD + tid] = hacc7;
        hacc0 = hacc1 = hacc2 = hacc3 = hacc4 = hacc5 = hacc6 = hacc7 = 0.f;
        // y projection ONCE per timestep from local weighted-h slice (linearity)
        {
            int o = tid >> 3, bl = tid & 7;
            float s = 0.f;
            #pragma unroll
            for (int jl = 0; jl < 16; jl++) s += acch[jl * 8 + bl] * wout_s[o * 16 + jl];
            atomicAdd(&g_yacc[((size_t)(bgbase + bl) * TT + t) * OUTF + o], s);
            if (tid < 16) {
                int idx = 512 + tid, o2 = idx >> 3, bl2 = idx & 7;
                float s2 = 0.f;
                #pragma unroll
                for (int jl = 0; jl < 16; jl++) s2 += acch[jl * 8 + bl2] * wout_s[o2 * 16 + jl];
                atomicAdd(&g_yacc[((size_t)(bgbase + bl2) * TT + t) * OUTF + o2], s2);
            }
        }
        if (js == 0 && tid < 8)
            pout[(size_t)(bgbase + tid) * TT + t] = nupd_s[tid] + rem_s[tid];
        __syncthreads();   // T-sync-Y: all acch readers done before reset (R12 race fix)
        if (tid < 128) { cs[tid] = accc[tid]; accc[tid] = 0.f; acch[tid] = 0.f; }
        if (tid < 8) { cum_s[tid] = 0.f; nupd_s[tid] = 0.f; rem_s[tid] = 0.f; done_s[tid] = 0; }
        if (t + 1 < TT && tid < GB * NIN) {
            int bb = tid / NIN, k = tid - bb * NIN;
            x_sh[bb * 52 + k] = x[((size_t)(bgbase + bb) * TT + (t + 1)) * NIN + k];
        }
        __syncthreads();   // T-sync-B
        if (t + 1 < TT) {
            float s = brow;
            #pragma unroll
            for (int k = 0; k < NIN; k++) s += x_sh[bl8 * 52 + k] * wih_s[rowl * 52 + k];
            gx_sh[rowl * 8 + bl8] = s;   // consumed by pointwise, after next sync 1
        }
    }

    // ---------------- epilogue: group barrier, then fused softmax ----------------
    __syncthreads();
    if (tid == 0) {
        __threadfence();                                   // drain REDs
        stcg_flag(&g_slot[bg][js][0], lgen + 1);
    } else if (tid >= 480) {
        const unsigned tgt = lgen + 1;
        for (;;) {
            unsigned v = ldcg_poll(&g_slot[bg][tid & 31][0]);
            if (__all_sync(0xffffffffu, v >= tgt)) break;
            __nanosleep(32);
        }
    }
    __syncthreads();
    lgen++;

    {   // 16 warps x 8 (b,t) pairs per CTA (128 total = this CTA's share of 4096)
        const int w = tid >> 5, lane = tid & 31;
        for (int k = 0; k < 8; k++) {
            int q    = js * 128 + w * 8 + k;       // 0..4095 within group
            int bloc = q >> 9, tt = q & 511;
            size_t base = ((size_t)(bgbase + bloc) * TT + tt) * OUTF;
            vb[w][lane]      = __ldcg(&g_yacc[base + lane])      + boutsh[lane];
            vb[w][32 + lane] = __ldcg(&g_yacc[base + 32 + lane]) + boutsh[32 + lane];
            if (lane < 2)
                vb[w][64 + lane] = __ldcg(&g_yacc[base + 64 + lane]) + boutsh[64 + lane];
            __syncwarp();
            if (lane < 6) {
                float m = -1e30f;
                #pragma unroll
                for (int q2 = 0; q2 < 11; q2++) m = fmaxf(m, vb[w][lane * 11 + q2]);
                float s = 0.f;
                #pragma unroll
                for (int q2 = 0; q2 < 11; q2++) s += expf(vb[w][lane * 11 + q2] - m);
                msm[w][lane] = m; mss[w][lane] = s;
            }
            __syncwarp();
            {
                int d0 = lane / 11, d1 = (32 + lane) / 11;
                out[base + lane]      = expf(vb[w][lane]      - msm[w][d0]) / mss[w][d0];
                out[base + 32 + lane] = expf(vb[w][32 + lane] - msm[w][d1]) / mss[w][d1];
                if (lane < 2)
                    out[base + 64 + lane] = expf(vb[w][64 + lane] - msm[w][5]) / mss[w][5];
            }
            __syncwarp();
        }
    }

    // ---------------- exit: reset barrier slots for the next graph replay ----------------
    __syncthreads();
    if (tid == 0) {
        __threadfence();
        unsigned a = atomicAdd(&g_exitcnt[bg * 32], 1u);
        if (a == 31u) {
            atomicExch(&g_exitcnt[bg * 32], 0u);
            for (int q = 0; q < NJS; q++) atomicExch(&g_slot[bg][q][0], 0u);
        }
    }
}

extern "C" void kernel_launch(void* const* d_in, const int* in_sizes, int n_in,
                              void* d_out, int out_size) {
    const float* x     = (const float*)d_in[0];
    const float* Wih   = (const float*)d_in[1];
    const float* Whh   = (const float*)d_in[2];
    const float* b     = (const float*)d_in[3];
    const float* Wout  = (const float*)d_in[4];
    const float* bout  = (const float*)d_in[5];
    const float* Whalt = (const float*)d_in[6];
    const float* bhalt = (const float*)d_in[7];
    float* out = (float*)d_out;

    cudaFuncSetAttribute(act_lstm_main, cudaFuncAttributeMaxDynamicSharedMemorySize,
                         DSM_FLOATS * 4);
    act_lstm_main<<<NCTA, NTHR, DSM_FLOATS * 4>>>(x, Wih, Whh, b, Wout, bout,
                                                  Whalt, bhalt, out);
}

// round 15
// speedup vs baseline: 2.0483x; 1.0640x over previous
#include <cuda_runtime.h>
#include <math.h>
#include <stdint.h>

#define NB    32
#define TT    512
#define NIN   50
#define HH    512
#define OUTF  66
#define MAXP  10
#define NJS   32
#define NBG   4
#define GB    8
#define NTHR  512
#define NCTA  128
#define PAD   516

__device__ float    g_hstep[2][NBG][HH][GB];     // parity h2 exchange, [j][b]
__device__ float    g_haltp[2][NBG][NJS][32];    // halt partials: [js][b*4+w] (float4/ (js,b))
__device__ unsigned g_wflag[NBG][NJS][4][32];    // per-producer-warp epoch flags, 128B apart
__device__ float    g_yacc[NB * TT * OUTF];
__device__ unsigned g_slot[NBG][NJS][32];
__device__ unsigned g_exitcnt[NBG * 32];

__device__ __forceinline__ float sigm(float v) { return 1.0f / (1.0f + __expf(-v)); }
__device__ __forceinline__ void ffma2(unsigned long long& d, unsigned long long a,
                                      unsigned long long b) {
    asm("fma.rn.f32x2 %0, %1, %2, %0;" : "+l"(d) : "l"(a), "l"(b));
}
__device__ __forceinline__ float2 unpk(unsigned long long v) {
    float2 r; asm("mov.b64 {%0, %1}, %2;" : "=f"(r.x), "=f"(r.y) : "l"(v)); return r;
}
// release/acquire flag ops; asm volatile + "memory" keeps polls in-loop (R9 lesson)
__device__ __forceinline__ unsigned ld_acq(const unsigned* p) {
    unsigned v;
    asm volatile("ld.acquire.gpu.global.u32 %0, [%1];" : "=r"(v) : "l"(p) : "memory");
    return v;
}
__device__ __forceinline__ void st_rel(unsigned* p, unsigned v) {
    asm volatile("st.release.gpu.global.u32 [%0], %1;" :: "l"(p), "r"(v) : "memory");
}

#define WHH_OFF    0
#define WIH_OFF    (64 * PAD)
#define WOUT_OFF   (WIH_OFF + 64 * 52)
#define WHALT_OFF  (WOUT_OFF + 66 * 16)
#define H_OFF      (WHALT_OFF + 16)
#define GX_OFF     (H_OFF + 8 * PAD)
#define DSM_FLOATS (GX_OFF + 512)

extern __shared__ float dsm[];

__global__ void __launch_bounds__(NTHR, 1)
act_lstm_main(const float* __restrict__ x,   const float* __restrict__ Wih,
              const float* __restrict__ Whh, const float* __restrict__ bias,
              const float* __restrict__ Wout,const float* __restrict__ bout,
              const float* __restrict__ Whalt,const float* __restrict__ bhaltp,
              float* __restrict__ out)
{
    const int bg = blockIdx.x >> 5, js = blockIdx.x & 31, bgbase = bg * GB;
    const int tid = threadIdx.x, lane = tid & 31, w = tid >> 5;
    const int rowl = tid >> 3, bl8 = tid & 7;
    const int grow = (rowl >> 4) * HH + js * 16 + (rowl & 15);
    const int b_own = lane & 7, jgrp = lane >> 3;          // ACT lane mapping
    const float bhalt = bhaltp[0];
    float* pout = out + (size_t)NB * TT * OUTF;

    float* whh_s = dsm + WHH_OFF;  float* wih_s  = dsm + WIH_OFF;
    float* wout_s = dsm + WOUT_OFF; float* whalt_s = dsm + WHALT_OFF;
    float* h_sh = dsm + H_OFF;     float* gx_sh  = dsm + GX_OFF;

    __shared__ float gate_sh[512];
    __shared__ float acch_sh[128];
    __shared__ float x_sh[GB * 52];
    __shared__ float boutsh[OUTF];
    __shared__ float vb[16][68];
    __shared__ float msm[16][6], mss[16][6];

    // ---------------- prologue ----------------
    for (int f4 = tid; f4 < 64 * 128; f4 += NTHR) {
        int r = f4 >> 7, kk = (f4 & 127) << 2;
        int gr = (r >> 4) * HH + js * 16 + (r & 15);
        float4 wv = *reinterpret_cast<const float4*>(Whh + (size_t)gr * HH + kk);
        *reinterpret_cast<float4*>(whh_s + r * PAD + kk) = wv;
    }
    for (int i = tid; i < 64 * 51; i += NTHR) {
        int r = i / 51, k = i - r * 51;
        int gr = (r >> 4) * HH + js * 16 + (r & 15);
        wih_s[r * 52 + k] = Wih[(size_t)gr * 51 + k];
    }
    for (int i = tid; i < OUTF * 16; i += NTHR)
        wout_s[i] = Wout[(size_t)(i >> 4) * HH + js * 16 + (i & 15)];
    if (tid < 16)   whalt_s[tid] = Whalt[js * 16 + tid];
    if (tid < OUTF) boutsh[tid]  = bout[tid];
    {   // zero this CTA's share of yacc (drained before peers' REDs by slot barrier)
        const int chunk = GB * TT * OUTF / NJS;
        float* base = g_yacc + (size_t)bgbase * TT * OUTF + (size_t)js * chunk;
        for (int i = tid; i < chunk; i += NTHR) __stcg(base + i, 0.0f);
    }
    #pragma unroll
    for (int i = 0; i < 8; i++) h_sh[i * PAD + tid] = 0.0f;
    for (int i = tid; i < GB * NIN; i += NTHR) {
        int bb = i / NIN, k = i - bb * NIN;
        x_sh[bb * 52 + k] = x[((size_t)(bgbase + bb) * TT) * NIN + k];
    }
    __syncthreads();

    const float brow = bias[grow];
    float flw0 = 0.f, flw1 = 0.f, flw2 = 0.f, flw3 = 0.f;
    if (tid < 128) {
        int jl = tid >> 3;
        flw0 = wih_s[jl * 52 + 50];        flw1 = wih_s[(16 + jl) * 52 + 50];
        flw2 = wih_s[(32 + jl) * 52 + 50]; flw3 = wih_s[(48 + jl) * 52 + 50];
    }
    {   float s = brow;
        #pragma unroll
        for (int k = 0; k < NIN; k++) s += x_sh[bl8 * 52 + k] * wih_s[rowl * 52 + k];
        gx_sh[rowl * 8 + bl8] = s;
    }
    // pre-loop group barrier (slot value 1)
    __syncthreads();
    if (tid == 0) st_rel(&g_slot[bg][js][0], 1u);
    else if (tid >= 480) {
        while (ld_acq(&g_slot[bg][lane][0]) < 1u) __nanosleep(32);
    }
    __syncthreads();

    unsigned estep = 1;
    float c_reg = 0.f, accc_reg = 0.f, acch_reg = 0.f, h2_reg = 0.f;
    float ha0=0.f,ha1=0.f,ha2=0.f,ha3=0.f,ha4=0.f,ha5=0.f,ha6=0.f,ha7=0.f;
    float cum_o = 0.f, pond_o = 0.f;
    int   done_o = 0;

    // ================= time loop =================
    for (int t = 0; t < TT; t++) {
        for (int n = 0; n < MAXP; n++) {
            const int par = estep & 1;
            __syncthreads();                               // S1: h_sh staged
            if (tid < 256) {                               // gate GEMM
                const int rp = tid >> 3, bl = tid & 7;
                const int r0 = rp * 2, r1 = r0 + 1;
                const ulonglong2* __restrict__ w0 =
                    reinterpret_cast<const ulonglong2*>(whh_s + r0 * PAD);
                const ulonglong2* __restrict__ w1 =
                    reinterpret_cast<const ulonglong2*>(whh_s + r1 * PAD);
                const ulonglong2* __restrict__ hp =
                    reinterpret_cast<const ulonglong2*>(h_sh + bl * PAD);
                unsigned long long a00=0ull,a01=0ull,a10=0ull,a11=0ull;
                #pragma unroll 8
                for (int k = 0; k < 128; k++) {
                    ulonglong2 hv = hp[k], wa = w0[k], wb = w1[k];
                    ffma2(a00, wa.x, hv.x); ffma2(a01, wa.y, hv.y);
                    ffma2(a10, wb.x, hv.x); ffma2(a11, wb.y, hv.y);
                }
                float2 u0=unpk(a00),u1=unpk(a01),u2=unpk(a10),u3=unpk(a11);
                gate_sh[r0 * 8 + bl] = (u0.x+u0.y)+(u1.x+u1.y);
                gate_sh[r1 * 8 + bl] = (u2.x+u2.y)+(u3.x+u3.y);
            }
            __syncthreads();                               // S2: gates ready
            if (tid < 128) {                               // pointwise + publish
                const int jl = tid >> 3, bl = tid & 7;
                const float fl = (n == 0) ? 1.0f : 0.0f;
                float gi = gate_sh[jl*8+bl]        + gx_sh[jl*8+bl]        + fl*flw0;
                float gf = gate_sh[(16+jl)*8+bl]   + gx_sh[(16+jl)*8+bl]   + fl*flw1;
                float gg = gate_sh[(32+jl)*8+bl]   + gx_sh[(32+jl)*8+bl]   + fl*flw2;
                float go = gate_sh[(48+jl)*8+bl]   + gx_sh[(48+jl)*8+bl]   + fl*flw3;
                float c2 = sigm(gf) * c_reg + sigm(gi) * tanhf(gg);
                float h2 = sigm(go) * tanhf(c2);
                c_reg = c2; h2_reg = h2;
                __stcg(&g_hstep[par][bg][js * 16 + jl][bl], h2);
                float hwv = h2 * whalt_s[jl];
                hwv += __shfl_xor_sync(0xffffffffu, hwv, 8);
                hwv += __shfl_xor_sync(0xffffffffu, hwv, 16);
                if (lane < 8)
                    __stcg(&g_haltp[par][bg][js][lane * 4 + w], hwv);
                __syncwarp();
                if (lane == 0) st_rel(&g_wflag[bg][js][w][0], estep);  // HB: bar→release
            } else if (tid >= 384) {                       // pollers: 1 flag/thread
                const int q = tid - 384;
                while (ld_acq(&g_wflag[bg][q >> 2][q & 3][0]) < estep) __nanosleep(32);
            }
            __syncthreads();                               // S3: all 128 flags seen
            // ---- loads ----
            float4 v0, v1;
            {   const float* hb = &g_hstep[par][bg][0][0];
                v0 = __ldcg(reinterpret_cast<const float4*>(hb + tid * 8));
                v1 = __ldcg(reinterpret_cast<const float4*>(hb + tid * 8 + 4));
            }
            // ---- replicated-lite ACT: lane owns batch b_own ----
            float hd = 0.f;
            {   const float4* hp4 = reinterpret_cast<const float4*>(&g_haltp[par][bg][0][0]);
                #pragma unroll
                for (int q = 0; q < 8; q++) {
                    float4 hv = __ldcg(&hp4[(jgrp + q * 4) * 8 + b_own]);
                    hd += (hv.x + hv.y) + (hv.z + hv.w);
                }
                hd += __shfl_xor_sync(0xffffffffu, hd, 8);
                hd += __shfl_xor_sync(0xffffffffu, hd, 16);
            }
            float halt = sigm(hd + bhalt);
            int wasdone = done_o;
            int halted  = ((cum_o + halt) > 0.99f) || (n == MAXP - 1);
            float p_own = wasdone ? 0.f : (halted ? (1.f - cum_o) : halt);
            pond_o += wasdone ? 0.f : 1.f;
            if (!wasdone && halted) pond_o += 1.f - cum_o;
            cum_o  += wasdone ? 0.f : halt;
            done_o  = wasdone || halted;
            int alldone = ((__ballot_sync(0xffffffffu, done_o) & 0xffu) == 0xffu);
            float p0=__shfl_sync(0xffffffffu,p_own,0), p1=__shfl_sync(0xffffffffu,p_own,1);
            float p2=__shfl_sync(0xffffffffu,p_own,2), p3=__shfl_sync(0xffffffffu,p_own,3);
            float p4=__shfl_sync(0xffffffffu,p_own,4), p5=__shfl_sync(0xffffffffu,p_own,5);
            float p6=__shfl_sync(0xffffffffu,p_own,6), p7=__shfl_sync(0xffffffffu,p_own,7);
            // ---- weighted accumulation (all in registers) ----
            ha0 += p0*v0.x; ha1 += p1*v0.y; ha2 += p2*v0.z; ha3 += p3*v0.w;
            ha4 += p4*v1.x; ha5 += p5*v1.y; ha6 += p6*v1.z; ha7 += p7*v1.w;
            if (tid < 128) {          // bl == b_own for these threads
                accc_reg += p_own * c_reg;
                acch_reg += p_own * h2_reg;
            }
            estep++;
            if (alldone) break;       // uniform across warps & CTAs
            h_sh[0*PAD+tid]=v0.x; h_sh[1*PAD+tid]=v0.y;
            h_sh[2*PAD+tid]=v0.z; h_sh[3*PAD+tid]=v0.w;
            h_sh[4*PAD+tid]=v1.x; h_sh[5*PAD+tid]=v1.y;
            h_sh[6*PAD+tid]=v1.z; h_sh[7*PAD+tid]=v1.w;
        }

        // ---------- timestep transition ----------
        h_sh[0*PAD+tid]=ha0; h_sh[1*PAD+tid]=ha1; h_sh[2*PAD+tid]=ha2; h_sh[3*PAD+tid]=ha3;
        h_sh[4*PAD+tid]=ha4; h_sh[5*PAD+tid]=ha5; h_sh[6*PAD+tid]=ha6; h_sh[7*PAD+tid]=ha7;
        ha0=ha1=ha2=ha3=ha4=ha5=ha6=ha7=0.f;
        if (tid < 128) {
            acch_sh[tid] = acch_reg;
            c_reg = accc_reg; accc_reg = 0.f; acch_reg = 0.f;
        }
        if (js == 0 && tid < 8)
            pout[(size_t)(bgbase + tid) * TT + t] = pond_o;   // lane==tid owns b=tid
        cum_o = 0.f; pond_o = 0.f; done_o = 0;
        if (t + 1 < TT && tid < GB * NIN) {
            int bb = tid / NIN, k = tid - bb * NIN;
            x_sh[bb * 52 + k] = x[((size_t)(bgbase + bb) * TT + (t + 1)) * NIN + k];
        }
        __syncthreads();                                   // T-A
        {   // y projection once per timestep (linearity of W_out)
            int o = tid >> 3, bl = tid & 7;
            float s = 0.f;
            #pragma unroll
            for (int jl = 0; jl < 16; jl++) s += acch_sh[jl * 8 + bl] * wout_s[o * 16 + jl];
            atomicAdd(&g_yacc[((size_t)(bgbase + bl) * TT + t) * OUTF + o], s);
            if (tid < 16) {
                int idx = 512 + tid, o2 = idx >> 3, bl2 = idx & 7;
                float s2 = 0.f;
                #pragma unroll
                for (int jl = 0; jl < 16; jl++) s2 += acch_sh[jl * 8 + bl2] * wout_s[o2 * 16 + jl];
                atomicAdd(&g_yacc[((size_t)(bgbase + bl2) * TT + t) * OUTF + o2], s2);
            }
        }
        if (t + 1 < TT) {
            float s = brow;
            #pragma unroll
            for (int k = 0; k < NIN; k++) s += x_sh[bl8 * 52 + k] * wih_s[rowl * 52 + k];
            gx_sh[rowl * 8 + bl8] = s;                     // read after next S1+S2
        }
    }

    // ---------------- epilogue: group barrier (slot=2) + fused softmax ----------------
    __syncthreads();
    if (tid == 0) st_rel(&g_slot[bg][js][0], 2u);          // release drains REDs
    else if (tid >= 480) {
        while (ld_acq(&g_slot[bg][lane][0]) < 2u) __nanosleep(32);
    }
    __syncthreads();
    {
        for (int k = 0; k < 8; k++) {
            int q = js * 128 + w * 8 + k;
            int bloc = q >> 9, tt = q & 511;
            size_t base = ((size_t)(bgbase + bloc) * TT + tt) * OUTF;
            vb[w][lane]      = __ldcg(&g_yacc[base + lane])      + boutsh[lane];
            vb[w][32 + lane] = __ldcg(&g_yacc[base + 32 + lane]) + boutsh[32 + lane];
            if (lane < 2)
                vb[w][64 + lane] = __ldcg(&g_yacc[base + 64 + lane]) + boutsh[64 + lane];
            __syncwarp();
            if (lane < 6) {
                float m = -1e30f;
                #pragma unroll
                for (int q2 = 0; q2 < 11; q2++) m = fmaxf(m, vb[w][lane * 11 + q2]);
                float s = 0.f;
                #pragma unroll
                for (int q2 = 0; q2 < 11; q2++) s += expf(vb[w][lane * 11 + q2] - m);
                msm[w][lane] = m; mss[w][lane] = s;
            }
            __syncwarp();
            {
                int d0 = lane / 11, d1 = (32 + lane) / 11;
                out[base + lane]      = expf(vb[w][lane]      - msm[w][d0]) / mss[w][d0];
                out[base + 32 + lane] = expf(vb[w][32 + lane] - msm[w][d1]) / mss[w][d1];
                if (lane < 2)
                    out[base + 64 + lane] = expf(vb[w][64 + lane] - msm[w][5]) / mss[w][5];
            }
            __syncwarp();
        }
    }

    // ---------------- exit: reset all flags for the next graph replay ----------------
    __syncthreads();
    if (tid == 0) {
        __threadfence();
        unsigned a = atomicAdd(&g_exitcnt[bg * 32], 1u);
        if (a == 31u) {
            atomicExch(&g_exitcnt[bg * 32], 0u);
            for (int q = 0; q < NJS; q++) {
                atomicExch(&g_slot[bg][q][0], 0u);
                for (int w2 = 0; w2 < 4; w2++) atomicExch(&g_wflag[bg][q][w2][0], 0u);
            }
        }
    }
}

extern "C" void kernel_launch(void* const* d_in, const int* in_sizes, int n_in,
                              void* d_out, int out_size) {
    const float* x     = (const float*)d_in[0];
    const float* Wih   = (const float*)d_in[1];
    const float* Whh   = (const float*)d_in[2];
    const float* b     = (const float*)d_in[3];
    const float* Wout  = (const float*)d_in[4];
    const float* bout  = (const float*)d_in[5];
    const float* Whalt = (const float*)d_in[6];
    const float* bhalt = (const float*)d_in[7];
    float* out = (float*)d_out;

    cudaFuncSetAttribute(act_lstm_main, cudaFuncAttributeMaxDynamicSharedMemorySize,
                         DSM_FLOATS * 4);
    act_lstm_main<<<NCTA, NTHR, DSM_FLOATS * 4>>>(x, Wih, Whh, b, Wout, bout,
                                                  Whalt, bhalt, out);
}